// round 1
// baseline (speedup 1.0000x reference)
#include <cuda_runtime.h>
#include <cstdint>

#define NN 4096
#define FF 32
#define NEG_SLOPE 0.2f
#define CAPW 160          // per-warp-region nonzero capacity (512 cols @ 1% -> mean 5.1)
#define KSPLIT 8

// ---------------- device scratch (static globals; no allocation) ----------------
__device__ float g_xw[2][2][NN * FF];     // [branch][k] : x @ W[k]
__device__ float g_xw0[NN * FF];          // x @ W0
__device__ float g_s1[2][NN];
__device__ float g_s2[2][NN];
__device__ float g_y[2][NN * FF];         // y = xw0 + L @ xw1
__device__ float g_ysum[2][FF];           // column sums of y (empty-row fallback)
__device__ unsigned short g_nzj[2][(size_t)NN * 8 * CAPW];  // per-row, per-warp-region col indices
__device__ int g_cnt[2][NN * 8];
__device__ float g_part[KSPLIT][NN * FF]; // P-GEMM k-split partials

__device__ __forceinline__ unsigned long long ffma2(unsigned long long a,
                                                    unsigned long long b,
                                                    unsigned long long c) {
    unsigned long long d;
    asm("fma.rn.f32x2 %0, %1, %2, %3;" : "=l"(d) : "l"(a), "l"(b), "l"(c));
    return d;
}
__device__ __forceinline__ unsigned long long pack2(float lo, float hi) {
    unsigned long long d;
    asm("mov.b64 %0, {%1, %2};" : "=l"(d) : "f"(lo), "f"(hi));
    return d;
}
__device__ __forceinline__ float2 unpack2(unsigned long long v) {
    float2 r;
    asm("mov.b64 {%0, %1}, %2;" : "=f"(r.x), "=f"(r.y) : "l"(v));
    return r;
}
__device__ __forceinline__ float warp_sum(float p) {
    #pragma unroll
    for (int d = 16; d; d >>= 1) p += __shfl_xor_sync(0xffffffffu, p, d);
    return p;
}

// ---------------- K1: xw[k] = x@W[k], xw0 = x@W0, s1/s2 vectors ----------------
__global__ void k_pre(const float* __restrict__ x, const float* __restrict__ W1,
                      const float* __restrict__ W2, const float* __restrict__ W0,
                      const float* __restrict__ att1, const float* __restrict__ att2) {
    int w = threadIdx.x >> 5, lane = threadIdx.x & 31;
    int i = blockIdx.x * 4 + w;
    float xv = x[i * FF + lane];

    float o0 = 0.f, o1 = 0.f, o2 = 0.f, o3 = 0.f, o4 = 0.f;
    #pragma unroll
    for (int f = 0; f < FF; f++) {
        float xf = __shfl_sync(0xffffffffu, xv, f);
        o0 += xf * __ldg(&W1[f * FF + lane]);
        o1 += xf * __ldg(&W1[1024 + f * FF + lane]);
        o2 += xf * __ldg(&W2[f * FF + lane]);
        o3 += xf * __ldg(&W2[1024 + f * FF + lane]);
        o4 += xf * __ldg(&W0[f * FF + lane]);
    }
    g_xw[0][0][i * FF + lane] = o0;
    g_xw[0][1][i * FF + lane] = o1;
    g_xw[1][0][i * FF + lane] = o2;
    g_xw[1][1][i * FF + lane] = o3;
    g_xw0[i * FF + lane] = o4;

    float p;
    p = warp_sum(o0 * __ldg(&att1[lane]) + o1 * __ldg(&att1[FF + lane]));
    if (lane == 0) g_s1[0][i] = p;
    p = warp_sum(o0 * __ldg(&att1[2 * FF + lane]) + o1 * __ldg(&att1[3 * FF + lane]));
    if (lane == 0) g_s2[0][i] = p;
    p = warp_sum(o2 * __ldg(&att2[lane]) + o3 * __ldg(&att2[FF + lane]));
    if (lane == 0) g_s1[1][i] = p;
    p = warp_sum(o2 * __ldg(&att2[2 * FF + lane]) + o3 * __ldg(&att2[3 * FF + lane]));
    if (lane == 0) g_s2[1][i] = p;
}

// ---------------- K2: y = xw0 + L@xw1, plus nonzero index list build ----------------
// One block per row. 8 warps; warp w scans columns [w*512, (w+1)*512).
__global__ void k_spmm(const float* __restrict__ L, int b) {
    int i = blockIdx.x;
    int w = threadIdx.x >> 5, lane = threadIdx.x & 31;
    const float* __restrict__ xw1 = g_xw[b][1];
    const float4* __restrict__ Lrow = reinterpret_cast<const float4*>(L + (size_t)i * NN);

    float acc = 0.f;
    int cnt = 0;
    unsigned short* nz = &g_nzj[b][((size_t)i * 8 + w) * CAPW];
    int cbase = w * 512;

    #pragma unroll
    for (int it = 0; it < 4; it++) {
        float4 v = Lrow[w * 128 + it * 32 + lane];
        float ve4[4] = {v.x, v.y, v.z, v.w};
        #pragma unroll
        for (int e = 0; e < 4; e++) {
            float ve = ve4[e];
            unsigned mask = __ballot_sync(0xffffffffu, ve != 0.f);
            if (ve != 0.f) {
                int pos = cnt + __popc(mask & ((1u << lane) - 1u));
                if (pos < CAPW)
                    nz[pos] = (unsigned short)(cbase + it * 128 + lane * 4 + e);
            }
            cnt += __popc(mask);
            while (mask) {
                int s = __ffs(mask) - 1;
                mask &= mask - 1;
                float val = __shfl_sync(0xffffffffu, ve, s);
                int col = cbase + it * 128 + s * 4 + e;
                acc += val * xw1[col * FF + lane];
            }
        }
    }

    __shared__ float ypart[8][FF];
    ypart[w][lane] = acc;
    if (lane == 0) g_cnt[b][i * 8 + w] = (cnt < CAPW) ? cnt : CAPW;
    __syncthreads();
    if (w == 0) {
        float s = g_xw[b][0][i * FF + lane];
        #pragma unroll
        for (int ww = 0; ww < 8; ww++) s += ypart[ww][lane];
        g_y[b][i * FF + lane] = s;
    }
}

// ---------------- K2b: deterministic column sums of y ----------------
__global__ void k_colsum() {
    int b = blockIdx.x;
    int col = threadIdx.x & 31, g = threadIdx.x >> 5;  // 32 groups x 32 cols
    float acc = 0.f;
    for (int r = g; r < NN; r += 32) acc += g_y[b][r * FF + col];
    __shared__ float s[32][32];
    s[g][col] = acc;
    __syncthreads();
    if (g == 0) {
        float t = 0.f;
        #pragma unroll
        for (int gg = 0; gg < 32; gg++) t += s[gg][col];
        g_ysum[b][col] = t;
    }
}

// ---------------- K3: online softmax over nonzeros + weighted gather ----------------
// One block (4 warps) per row. Warp w handles index regions {w, w+4}.
__global__ void k_attn(int b, float* __restrict__ out, int add) {
    int i = blockIdx.x;
    int w = threadIdx.x >> 5, lane = threadIdx.x & 31;
    float s1i = g_s1[b][i];
    const float* __restrict__ s2 = g_s2[b];
    const float* __restrict__ y = g_y[b];
    const float NEGINF = __int_as_float(0xff800000u);

    float m = NEGINF, l = 0.f, z = 0.f;
    #pragma unroll
    for (int rr = 0; rr < 2; rr++) {
        int reg = w + rr * 4;
        int cnt = g_cnt[b][i * 8 + reg];
        const unsigned short* __restrict__ nz = &g_nzj[b][((size_t)i * 8 + reg) * CAPW];
        for (int p = 0; p < cnt; p++) {
            int j = nz[p];
            float e = s1i + s2[j];
            float ev = e > 0.f ? e : NEG_SLOPE * e;
            float nm = fmaxf(m, ev);
            float sc = __expf(m - nm);
            float pw = __expf(ev - nm);
            float yv = y[j * FF + lane];
            l = l * sc + pw;
            z = z * sc + pw * yv;
            m = nm;
        }
    }

    __shared__ float sm[4], sl[4], sz[4][FF];
    if (lane == 0) { sm[w] = m; sl[w] = l; }
    sz[w][lane] = z;
    __syncthreads();
    if (w == 0) {
        float M = fmaxf(fmaxf(sm[0], sm[1]), fmaxf(sm[2], sm[3]));
        float val;
        if (M == NEGINF) {
            val = g_ysum[b][lane] * (1.f / NN);   // fully-masked row: uniform softmax
        } else {
            float Ls = 0.f, Z = 0.f;
            #pragma unroll
            for (int ww = 0; ww < 4; ww++) {
                float sc = __expf(sm[ww] - M);
                Ls += sl[ww] * sc;
                Z += sz[ww][lane] * sc;
            }
            val = Z / Ls;
        }
        if (add) out[i * FF + lane] += val;
        else     out[i * FF + lane] = val;
    }
}

// ---------------- K4: partial[ks] = P[:, kslice] @ xw0[kslice, :], f32x2 FMA ----------------
#define BM 64
#define BK 32
__global__ void k_pgemm(const float* __restrict__ P) {
    __shared__ __align__(16) float Ps[BK][BM + 4];            // transposed, pad 4 -> 68
    __shared__ __align__(16) unsigned long long Bs[BK][FF];   // pre-duplicated (b,b) pairs

    int rb = blockIdx.x * BM;
    int k0 = blockIdx.y * (NN / KSPLIT);
    int t = threadIdx.x;
    int colq = t & 15;   // column pair index (cols 2q, 2q+1)
    int rowg = t >> 4;   // 16 groups of 4 rows

    unsigned long long a00 = 0ull, a01 = 0ull, a10 = 0ull, a11 = 0ull;

    const float4* __restrict__ P4 = reinterpret_cast<const float4*>(P);
    const float4* __restrict__ B4 = reinterpret_cast<const float4*>(g_xw0);

    for (int kt = 0; kt < (NN / KSPLIT) / BK; kt++) {
        int kk = k0 + kt * BK;
        // load P tile [BM x BK], store transposed
        {
            int row = t >> 3, c4 = t & 7;
            float4 v = P4[((size_t)(rb + row) * NN + kk) / 4 + c4];
            Ps[c4 * 4 + 0][row] = v.x; Ps[c4 * 4 + 1][row] = v.y;
            Ps[c4 * 4 + 2][row] = v.z; Ps[c4 * 4 + 3][row] = v.w;
            int row2 = row + 32;
            float4 u = P4[((size_t)(rb + row2) * NN + kk) / 4 + c4];
            Ps[c4 * 4 + 0][row2] = u.x; Ps[c4 * 4 + 1][row2] = u.y;
            Ps[c4 * 4 + 2][row2] = u.z; Ps[c4 * 4 + 3][row2] = u.w;
        }
        // load B tile [BK x FF] as duplicated pairs
        {
            int bk = t >> 3, bc4 = t & 7;
            float4 v = B4[(size_t)(kk + bk) * (FF / 4) + bc4];
            Bs[bk][bc4 * 4 + 0] = pack2(v.x, v.x);
            Bs[bk][bc4 * 4 + 1] = pack2(v.y, v.y);
            Bs[bk][bc4 * 4 + 2] = pack2(v.z, v.z);
            Bs[bk][bc4 * 4 + 3] = pack2(v.w, v.w);
        }
        __syncthreads();
        #pragma unroll
        for (int k = 0; k < BK; k++) {
            ulonglong2 pp = *reinterpret_cast<const ulonglong2*>(&Ps[k][rowg * 4]);
            unsigned long long bb0 = Bs[k][colq * 2];
            unsigned long long bb1 = Bs[k][colq * 2 + 1];
            a00 = ffma2(pp.x, bb0, a00);
            a01 = ffma2(pp.y, bb0, a01);
            a10 = ffma2(pp.x, bb1, a10);
            a11 = ffma2(pp.y, bb1, a11);
        }
        __syncthreads();
    }

    int r0 = rb + rowg * 4;
    int c = colq * 2;
    float* __restrict__ outp = g_part[blockIdx.y];
    float2 f;
    f = unpack2(a00); outp[(r0 + 0) * FF + c] = f.x;     outp[(r0 + 1) * FF + c] = f.y;
    f = unpack2(a01); outp[(r0 + 2) * FF + c] = f.x;     outp[(r0 + 3) * FF + c] = f.y;
    f = unpack2(a10); outp[(r0 + 0) * FF + c + 1] = f.x; outp[(r0 + 1) * FF + c + 1] = f.y;
    f = unpack2(a11); outp[(r0 + 2) * FF + c + 1] = f.x; outp[(r0 + 3) * FF + c + 1] = f.y;
}

// ---------------- K5: out += sum of k-split partials (fixed order) ----------------
__global__ void k_final(float* __restrict__ out) {
    int idx = blockIdx.x * blockDim.x + threadIdx.x;  // over NN*FF/4 float4s
    float4 o = reinterpret_cast<float4*>(out)[idx];
    #pragma unroll
    for (int s = 0; s < KSPLIT; s++) {
        float4 p = reinterpret_cast<const float4*>(g_part[s])[idx];
        o.x += p.x; o.y += p.y; o.z += p.z; o.w += p.w;
    }
    reinterpret_cast<float4*>(out)[idx] = o;
}

extern "C" void kernel_launch(void* const* d_in, const int* in_sizes, int n_in,
                              void* d_out, int out_size) {
    const float* x    = (const float*)d_in[0];
    const float* Ld   = (const float*)d_in[1];
    const float* Lu   = (const float*)d_in[2];
    const float* P    = (const float*)d_in[3];
    const float* W1   = (const float*)d_in[4];
    const float* W2   = (const float*)d_in[5];
    const float* W0   = (const float*)d_in[6];
    const float* att1 = (const float*)d_in[7];
    const float* att2 = (const float*)d_in[8];
    float* out = (float*)d_out;

    k_pre<<<NN / 4, 128>>>(x, W1, W2, W0, att1, att2);
    k_pgemm<<<dim3(NN / BM, KSPLIT), 256>>>(P);
    k_spmm<<<NN, 256>>>(Ld, 0);
    k_spmm<<<NN, 256>>>(Lu, 1);
    k_colsum<<<2, 1024>>>();
    k_attn<<<NN, 128>>>(0, out, 0);
    k_attn<<<NN, 128>>>(1, out, 1);
    k_final<<<NN * FF / 4 / 256, 256>>>(out);
}

// round 2
// speedup vs baseline: 1.0103x; 1.0103x over previous
#include <cuda_runtime.h>
#include <cstdint>

#define NN 4096
#define FF 32
#define NEG_SLOPE 0.2f
#define CAPW 160          // per-warp-region nonzero capacity (512 cols @ 1% -> mean 5.1)
#define KSPLIT 8

// ---------------- device scratch (static globals; no allocation) ----------------
__device__ float g_xw[2][2][NN * FF];     // [branch][k] : x @ W[k]
__device__ float g_xw0[NN * FF];          // x @ W0
__device__ float g_s1[2][NN];
__device__ float g_s2[2][NN];
__device__ float g_y[2][NN * FF];         // y = xw0 + L @ xw1
__device__ float g_ysum[2][FF];           // column sums of y (empty-row fallback)
__device__ unsigned short g_nzj[2][(size_t)NN * 8 * CAPW];  // per-row, per-warp-region col indices
__device__ int g_cnt[2][NN * 8];
__device__ float g_part[KSPLIT][NN * FF]; // P-GEMM k-split partials

__device__ __forceinline__ unsigned long long ffma2(unsigned long long a,
                                                    unsigned long long b,
                                                    unsigned long long c) {
    unsigned long long d;
    asm("fma.rn.f32x2 %0, %1, %2, %3;" : "=l"(d) : "l"(a), "l"(b), "l"(c));
    return d;
}
__device__ __forceinline__ unsigned long long pack2(float lo, float hi) {
    unsigned long long d;
    asm("mov.b64 %0, {%1, %2};" : "=l"(d) : "f"(lo), "f"(hi));
    return d;
}
__device__ __forceinline__ float2 unpack2(unsigned long long v) {
    float2 r;
    asm("mov.b64 {%0, %1}, %2;" : "=f"(r.x), "=f"(r.y) : "l"(v));
    return r;
}
__device__ __forceinline__ float warp_sum(float p) {
    #pragma unroll
    for (int d = 16; d; d >>= 1) p += __shfl_xor_sync(0xffffffffu, p, d);
    return p;
}

// ---------------- K1: xw[k] = x@W[k], xw0 = x@W0, s1/s2 vectors ----------------
__global__ void k_pre(const float* __restrict__ x, const float* __restrict__ W1,
                      const float* __restrict__ W2, const float* __restrict__ W0,
                      const float* __restrict__ att1, const float* __restrict__ att2) {
    int w = threadIdx.x >> 5, lane = threadIdx.x & 31;
    int i = blockIdx.x * 4 + w;
    float xv = x[i * FF + lane];

    float o0 = 0.f, o1 = 0.f, o2 = 0.f, o3 = 0.f, o4 = 0.f;
    #pragma unroll
    for (int f = 0; f < FF; f++) {
        float xf = __shfl_sync(0xffffffffu, xv, f);
        o0 += xf * __ldg(&W1[f * FF + lane]);
        o1 += xf * __ldg(&W1[1024 + f * FF + lane]);
        o2 += xf * __ldg(&W2[f * FF + lane]);
        o3 += xf * __ldg(&W2[1024 + f * FF + lane]);
        o4 += xf * __ldg(&W0[f * FF + lane]);
    }
    g_xw[0][0][i * FF + lane] = o0;
    g_xw[0][1][i * FF + lane] = o1;
    g_xw[1][0][i * FF + lane] = o2;
    g_xw[1][1][i * FF + lane] = o3;
    g_xw0[i * FF + lane] = o4;

    float p;
    p = warp_sum(o0 * __ldg(&att1[lane]) + o1 * __ldg(&att1[FF + lane]));
    if (lane == 0) g_s1[0][i] = p;
    p = warp_sum(o0 * __ldg(&att1[2 * FF + lane]) + o1 * __ldg(&att1[3 * FF + lane]));
    if (lane == 0) g_s2[0][i] = p;
    p = warp_sum(o2 * __ldg(&att2[lane]) + o3 * __ldg(&att2[FF + lane]));
    if (lane == 0) g_s1[1][i] = p;
    p = warp_sum(o2 * __ldg(&att2[2 * FF + lane]) + o3 * __ldg(&att2[3 * FF + lane]));
    if (lane == 0) g_s2[1][i] = p;
}

// ---------------- K2: y = xw0 + L@xw1, plus nonzero index list build ----------------
// One block per row. 8 warps; warp w scans columns [w*512, (w+1)*512).
__global__ void k_spmm(const float* __restrict__ L, int b) {
    int i = blockIdx.x;
    int w = threadIdx.x >> 5, lane = threadIdx.x & 31;
    const float* __restrict__ xw1 = g_xw[b][1];
    const float4* __restrict__ Lrow = reinterpret_cast<const float4*>(L + (size_t)i * NN);

    float acc = 0.f;
    int cnt = 0;
    unsigned short* nz = &g_nzj[b][((size_t)i * 8 + w) * CAPW];
    int cbase = w * 512;

    #pragma unroll
    for (int it = 0; it < 4; it++) {
        float4 v = Lrow[w * 128 + it * 32 + lane];
        float ve4[4] = {v.x, v.y, v.z, v.w};
        #pragma unroll
        for (int e = 0; e < 4; e++) {
            float ve = ve4[e];
            unsigned mask = __ballot_sync(0xffffffffu, ve != 0.f);
            if (ve != 0.f) {
                int pos = cnt + __popc(mask & ((1u << lane) - 1u));
                if (pos < CAPW)
                    nz[pos] = (unsigned short)(cbase + it * 128 + lane * 4 + e);
            }
            cnt += __popc(mask);
            while (mask) {
                int s = __ffs(mask) - 1;
                mask &= mask - 1;
                float val = __shfl_sync(0xffffffffu, ve, s);
                int col = cbase + it * 128 + s * 4 + e;
                acc += val * xw1[col * FF + lane];
            }
        }
    }

    __shared__ float ypart[8][FF];
    ypart[w][lane] = acc;
    if (lane == 0) g_cnt[b][i * 8 + w] = (cnt < CAPW) ? cnt : CAPW;
    __syncthreads();
    if (w == 0) {
        float s = g_xw[b][0][i * FF + lane];
        #pragma unroll
        for (int ww = 0; ww < 8; ww++) s += ypart[ww][lane];
        g_y[b][i * FF + lane] = s;
    }
}

// ---------------- K2b: deterministic column sums of y ----------------
__global__ void k_colsum() {
    int b = blockIdx.x;
    int col = threadIdx.x & 31, g = threadIdx.x >> 5;  // 32 groups x 32 cols
    float acc = 0.f;
    for (int r = g; r < NN; r += 32) acc += g_y[b][r * FF + col];
    __shared__ float s[32][32];
    s[g][col] = acc;
    __syncthreads();
    if (g == 0) {
        float t = 0.f;
        #pragma unroll
        for (int gg = 0; gg < 32; gg++) t += s[gg][col];
        g_ysum[b][col] = t;
    }
}

// ---------------- K3: online softmax over nonzeros + weighted gather ----------------
// One block (4 warps) per row. Warp w handles index regions {w, w+4}.
__global__ void k_attn(int b, float* __restrict__ out, int add) {
    int i = blockIdx.x;
    int w = threadIdx.x >> 5, lane = threadIdx.x & 31;
    float s1i = g_s1[b][i];
    const float* __restrict__ s2 = g_s2[b];
    const float* __restrict__ y = g_y[b];
    const float NEGINF = __int_as_float(0xff800000u);

    float m = NEGINF, l = 0.f, z = 0.f;
    #pragma unroll
    for (int rr = 0; rr < 2; rr++) {
        int reg = w + rr * 4;
        int cnt = g_cnt[b][i * 8 + reg];
        const unsigned short* __restrict__ nz = &g_nzj[b][((size_t)i * 8 + reg) * CAPW];
        for (int p = 0; p < cnt; p++) {
            int j = nz[p];
            float e = s1i + s2[j];
            float ev = e > 0.f ? e : NEG_SLOPE * e;
            float nm = fmaxf(m, ev);
            float sc = __expf(m - nm);
            float pw = __expf(ev - nm);
            float yv = y[j * FF + lane];
            l = l * sc + pw;
            z = z * sc + pw * yv;
            m = nm;
        }
    }

    __shared__ float sm[4], sl[4], sz[4][FF];
    if (lane == 0) { sm[w] = m; sl[w] = l; }
    sz[w][lane] = z;
    __syncthreads();
    if (w == 0) {
        float M = fmaxf(fmaxf(sm[0], sm[1]), fmaxf(sm[2], sm[3]));
        float val;
        if (M == NEGINF) {
            val = g_ysum[b][lane] * (1.f / NN);   // fully-masked row: uniform softmax
        } else {
            float Ls = 0.f, Z = 0.f;
            #pragma unroll
            for (int ww = 0; ww < 4; ww++) {
                float sc = __expf(sm[ww] - M);
                Ls += sl[ww] * sc;
                Z += sz[ww][lane] * sc;
            }
            val = Z / Ls;
        }
        if (add) out[i * FF + lane] += val;
        else     out[i * FF + lane] = val;
    }
}

// ---------------- K4: partial[ks] = P[:, kslice] @ xw0[kslice, :], f32x2 FMA ----------------
#define BM 64
#define BK 32
__global__ void k_pgemm(const float* __restrict__ P) {
    __shared__ __align__(16) float Ps[BK][BM + 4];            // transposed, pad 4 -> 68
    __shared__ __align__(16) unsigned long long Bs[BK][FF];   // pre-duplicated (b,b) pairs

    int rb = blockIdx.x * BM;
    int k0 = blockIdx.y * (NN / KSPLIT);
    int t = threadIdx.x;
    int colq = t & 15;   // column pair index (cols 2q, 2q+1)
    int rowg = t >> 4;   // 16 groups of 4 rows

    unsigned long long a00 = 0ull, a01 = 0ull, a10 = 0ull, a11 = 0ull;

    const float4* __restrict__ P4 = reinterpret_cast<const float4*>(P);
    const float4* __restrict__ B4 = reinterpret_cast<const float4*>(g_xw0);

    for (int kt = 0; kt < (NN / KSPLIT) / BK; kt++) {
        int kk = k0 + kt * BK;
        // load P tile [BM x BK], store transposed
        {
            int row = t >> 3, c4 = t & 7;
            float4 v = P4[((size_t)(rb + row) * NN + kk) / 4 + c4];
            Ps[c4 * 4 + 0][row] = v.x; Ps[c4 * 4 + 1][row] = v.y;
            Ps[c4 * 4 + 2][row] = v.z; Ps[c4 * 4 + 3][row] = v.w;
            int row2 = row + 32;
            float4 u = P4[((size_t)(rb + row2) * NN + kk) / 4 + c4];
            Ps[c4 * 4 + 0][row2] = u.x; Ps[c4 * 4 + 1][row2] = u.y;
            Ps[c4 * 4 + 2][row2] = u.z; Ps[c4 * 4 + 3][row2] = u.w;
        }
        // load B tile [BK x FF] as duplicated pairs
        {
            int bk = t >> 3, bc4 = t & 7;
            float4 v = B4[(size_t)(kk + bk) * (FF / 4) + bc4];
            Bs[bk][bc4 * 4 + 0] = pack2(v.x, v.x);
            Bs[bk][bc4 * 4 + 1] = pack2(v.y, v.y);
            Bs[bk][bc4 * 4 + 2] = pack2(v.z, v.z);
            Bs[bk][bc4 * 4 + 3] = pack2(v.w, v.w);
        }
        __syncthreads();
        #pragma unroll
        for (int k = 0; k < BK; k++) {
            ulonglong2 pp = *reinterpret_cast<const ulonglong2*>(&Ps[k][rowg * 4]);
            unsigned long long bb0 = Bs[k][colq * 2];
            unsigned long long bb1 = Bs[k][colq * 2 + 1];
            a00 = ffma2(pp.x, bb0, a00);
            a01 = ffma2(pp.y, bb0, a01);
            a10 = ffma2(pp.x, bb1, a10);
            a11 = ffma2(pp.y, bb1, a11);
        }
        __syncthreads();
    }

    int r0 = rb + rowg * 4;
    int c = colq * 2;
    float* __restrict__ outp = g_part[blockIdx.y];
    float2 f;
    f = unpack2(a00); outp[(r0 + 0) * FF + c] = f.x;     outp[(r0 + 1) * FF + c] = f.y;
    f = unpack2(a01); outp[(r0 + 2) * FF + c] = f.x;     outp[(r0 + 3) * FF + c] = f.y;
    f = unpack2(a10); outp[(r0 + 0) * FF + c + 1] = f.x; outp[(r0 + 1) * FF + c + 1] = f.y;
    f = unpack2(a11); outp[(r0 + 2) * FF + c + 1] = f.x; outp[(r0 + 3) * FF + c + 1] = f.y;
}

// ---------------- K5: out += sum of k-split partials (fixed order) ----------------
__global__ void k_final(float* __restrict__ out) {
    int idx = blockIdx.x * blockDim.x + threadIdx.x;  // over NN*FF/4 float4s
    float4 o = reinterpret_cast<float4*>(out)[idx];
    #pragma unroll
    for (int s = 0; s < KSPLIT; s++) {
        float4 p = reinterpret_cast<const float4*>(g_part[s])[idx];
        o.x += p.x; o.y += p.y; o.z += p.z; o.w += p.w;
    }
    reinterpret_cast<float4*>(out)[idx] = o;
}

extern "C" void kernel_launch(void* const* d_in, const int* in_sizes, int n_in,
                              void* d_out, int out_size) {
    const float* x    = (const float*)d_in[0];
    const float* Ld   = (const float*)d_in[1];
    const float* Lu   = (const float*)d_in[2];
    const float* P    = (const float*)d_in[3];
    const float* W1   = (const float*)d_in[4];
    const float* W2   = (const float*)d_in[5];
    const float* W0   = (const float*)d_in[6];
    const float* att1 = (const float*)d_in[7];
    const float* att2 = (const float*)d_in[8];
    float* out = (float*)d_out;

    k_pre<<<NN / 4, 128>>>(x, W1, W2, W0, att1, att2);
    k_pgemm<<<dim3(NN / BM, KSPLIT), 256>>>(P);
    k_spmm<<<NN, 256>>>(Ld, 0);
    k_spmm<<<NN, 256>>>(Lu, 1);
    k_colsum<<<2, 1024>>>();
    k_attn<<<NN, 128>>>(0, out, 0);
    k_attn<<<NN, 128>>>(1, out, 1);
    k_final<<<NN * FF / 4 / 256, 256>>>(out);
}

// round 3
// speedup vs baseline: 1.1222x; 1.1108x over previous
#include <cuda_runtime.h>
#include <cstdint>

typedef unsigned long long ull;
typedef unsigned short u16;

#define NN 4096
#define FF 32
#define NEG_SLOPE 0.2f
#define CAPR 64
#define KSPLIT 8
#define PGB 128
#define RP 264
#define BPITCH 46

__device__ float g_xw[2][2][NN * FF];
__device__ float g_xw0[NN * FF];
__device__ float g_s1[2][NN];
__device__ float g_s2[2][NN];
__device__ float g_y[2][NN * FF];
__device__ float g_ysum[2][FF];
__device__ u16   g_nzj[2][(size_t)NN * 4 * CAPR];
__device__ int   g_cnt[2][NN * 4];
__device__ float g_part[KSPLIT][NN * FF];

__device__ __forceinline__ ull ffma2(ull a, ull b, ull c) {
    ull d;
    asm("fma.rn.f32x2 %0, %1, %2, %3;" : "=l"(d) : "l"(a), "l"(b), "l"(c));
    return d;
}
__device__ __forceinline__ ull pack2(float lo, float hi) {
    ull d;
    asm("mov.b64 %0, {%1, %2};" : "=l"(d) : "f"(lo), "f"(hi));
    return d;
}
__device__ __forceinline__ float2 unpack2(ull v) {
    float2 r;
    asm("mov.b64 {%0, %1}, %2;" : "=f"(r.x), "=f"(r.y) : "l"(v));
    return r;
}
__device__ __forceinline__ float warp_sum(float p) {
    #pragma unroll
    for (int d = 16; d; d >>= 1) p += __shfl_xor_sync(0xffffffffu, p, d);
    return p;
}

// ---------------- K1: xw[k] = x@W[k], xw0 = x@W0, s1/s2 vectors ----------------
__global__ void k_pre(const float* __restrict__ x, const float* __restrict__ W1,
                      const float* __restrict__ W2, const float* __restrict__ W0,
                      const float* __restrict__ att1, const float* __restrict__ att2) {
    int w = threadIdx.x >> 5, lane = threadIdx.x & 31;
    int i = blockIdx.x * 4 + w;
    float xv = x[i * FF + lane];

    float o0 = 0.f, o1 = 0.f, o2 = 0.f, o3 = 0.f, o4 = 0.f;
    #pragma unroll
    for (int f = 0; f < FF; f++) {
        float xf = __shfl_sync(0xffffffffu, xv, f);
        o0 += xf * __ldg(&W1[f * FF + lane]);
        o1 += xf * __ldg(&W1[1024 + f * FF + lane]);
        o2 += xf * __ldg(&W2[f * FF + lane]);
        o3 += xf * __ldg(&W2[1024 + f * FF + lane]);
        o4 += xf * __ldg(&W0[f * FF + lane]);
    }
    g_xw[0][0][i * FF + lane] = o0;
    g_xw[0][1][i * FF + lane] = o1;
    g_xw[1][0][i * FF + lane] = o2;
    g_xw[1][1][i * FF + lane] = o3;
    g_xw0[i * FF + lane] = o4;

    float p;
    p = warp_sum(o0 * __ldg(&att1[lane]) + o1 * __ldg(&att1[FF + lane]));
    if (lane == 0) g_s1[0][i] = p;
    p = warp_sum(o0 * __ldg(&att1[2 * FF + lane]) + o1 * __ldg(&att1[3 * FF + lane]));
    if (lane == 0) g_s2[0][i] = p;
    p = warp_sum(o2 * __ldg(&att2[lane]) + o3 * __ldg(&att2[FF + lane]));
    if (lane == 0) g_s1[1][i] = p;
    p = warp_sum(o2 * __ldg(&att2[2 * FF + lane]) + o3 * __ldg(&att2[3 * FF + lane]));
    if (lane == 0) g_s2[1][i] = p;
}

// ---------------- K2 fused: pgemm (blocks 0..PGB-1) + spmm (rest) ----------------
__global__ __launch_bounds__(256) void k_mid(const float* __restrict__ P,
                                             const float* __restrict__ Ld,
                                             const float* __restrict__ Lu) {
    __shared__ __align__(16) float Ps[32 * RP];       // 33792 B
    __shared__ __align__(16) ull   Bs[32 * BPITCH];   // 11776 B
    int bid = blockIdx.x, t = threadIdx.x;

    if (bid < PGB) {
        // ---- P-GEMM role: g_part[ks] = P[:, ks-slice] @ xw0[slice, :] ----
        int rowblk = bid >> 3, ks = bid & 7;
        int rb = rowblk * 256, k0 = ks * 512;
        int c4 = t & 7, row0 = t >> 3;     // loader mapping
        int colq = t & 7, rowg = t >> 3;   // compute mapping
        const float4* __restrict__ P4 = (const float4*)P;
        const float4* __restrict__ B4 = (const float4*)g_xw0;

        ull acc[4][4];
        #pragma unroll
        for (int i = 0; i < 4; i++)
            #pragma unroll
            for (int j = 0; j < 4; j++) acc[i][j] = 0ull;

        float4 pv[8]; float4 bv;
        {
            int kk = k0;
            #pragma unroll
            for (int it = 0; it < 8; it++)
                pv[it] = P4[(size_t)(rb + row0 + it * 32) * (NN / 4) + (kk >> 2) + c4];
            bv = B4[(size_t)(kk + row0) * (FF / 4) + c4];
        }
        for (int kt = 0; kt < 16; kt++) {
            int sw = (c4 & 3) << 3;
            #pragma unroll
            for (int it = 0; it < 8; it++) {
                int r = (row0 ^ sw) + it * 32;
                Ps[(4 * c4 + 0) * RP + r] = pv[it].x;
                Ps[(4 * c4 + 1) * RP + r] = pv[it].y;
                Ps[(4 * c4 + 2) * RP + r] = pv[it].z;
                Ps[(4 * c4 + 3) * RP + r] = pv[it].w;
            }
            {
                ull* bp = &Bs[row0 * BPITCH + c4 * 6];
                bp[0] = pack2(bv.x, bv.x); bp[1] = pack2(bv.y, bv.y);
                bp[2] = pack2(bv.z, bv.z); bp[3] = pack2(bv.w, bv.w);
            }
            __syncthreads();
            if (kt < 15) {
                int kk = k0 + (kt + 1) * 32;
                #pragma unroll
                for (int it = 0; it < 8; it++)
                    pv[it] = P4[(size_t)(rb + row0 + it * 32) * (NN / 4) + (kk >> 2) + c4];
                bv = B4[(size_t)(kk + row0) * (FF / 4) + c4];
            }
            #pragma unroll
            for (int k = 0; k < 32; k++) {
                int swk = ((k >> 2) & 3) << 3;
                const float* pr = &Ps[k * RP + ((rowg * 8) ^ swk)];
                ulonglong2 pA = *(const ulonglong2*)pr;
                ulonglong2 pB = *(const ulonglong2*)(pr + 4);
                const ull* bp = &Bs[k * BPITCH + colq * 6];
                ulonglong2 bA = *(const ulonglong2*)bp;
                ulonglong2 bB = *(const ulonglong2*)(bp + 2);
                ull pp[4] = {pA.x, pA.y, pB.x, pB.y};
                ull bb[4] = {bA.x, bA.y, bB.x, bB.y};
                #pragma unroll
                for (int i = 0; i < 4; i++)
                    #pragma unroll
                    for (int j = 0; j < 4; j++)
                        acc[i][j] = ffma2(pp[i], bb[j], acc[i][j]);
            }
            __syncthreads();
        }
        float* __restrict__ outp = g_part[ks];
        int r0 = rb + rowg * 8, c0 = colq * 4;
        #pragma unroll
        for (int i = 0; i < 4; i++)
            #pragma unroll
            for (int j = 0; j < 4; j++) {
                float2 f = unpack2(acc[i][j]);
                outp[(size_t)(r0 + 2 * i) * FF + c0 + j]     = f.x;
                outp[(size_t)(r0 + 2 * i + 1) * FF + c0 + j] = f.y;
            }
    } else {
        // ---- SpMM role: y = xw0 + L@xw1, exact nz column lists ----
        int sb = bid - PGB;
        int b = sb >> 11;
        int w = t >> 5, lane = t & 31;
        int row = ((sb & 2047) << 1) + (w >> 2);
        int r = w & 3;
        const float* __restrict__ L = b ? Lu : Ld;
        const float4* __restrict__ Lr4 = (const float4*)(L + (size_t)row * NN + r * 1024);
        float4 v[8];
        #pragma unroll
        for (int it = 0; it < 8; it++) v[it] = Lr4[it * 32 + lane];

        const float* __restrict__ xw1 = g_xw[b][1];
        int regidx = row * 4 + r;
        u16* __restrict__ nz = &g_nzj[b][(size_t)regidx * CAPR];
        int cbase = r * 1024;
        int cnt = 0; float acc = 0.f;
        #pragma unroll
        for (int it = 0; it < 8; it++) {
            float4 q = v[it];
            bool any = (q.x != 0.f) || (q.y != 0.f) || (q.z != 0.f) || (q.w != 0.f);
            unsigned mask = __ballot_sync(0xffffffffu, any);
            while (mask) {
                int s = __ffs(mask) - 1; mask &= mask - 1;
                float u0 = __shfl_sync(0xffffffffu, q.x, s);
                float u1 = __shfl_sync(0xffffffffu, q.y, s);
                float u2 = __shfl_sync(0xffffffffu, q.z, s);
                float u3 = __shfl_sync(0xffffffffu, q.w, s);
                int col0 = cbase + it * 128 + s * 4;
                float uv[4] = {u0, u1, u2, u3};
                #pragma unroll
                for (int e = 0; e < 4; e++) {
                    if (uv[e] != 0.f) {   // uniform across warp
                        acc += uv[e] * xw1[(size_t)(col0 + e) * FF + lane];
                        if (lane == 0 && cnt < CAPR) nz[cnt] = (u16)(col0 + e);
                        cnt++;
                    }
                }
            }
        }
        if (cnt > CAPR) cnt = CAPR;
        if (lane == 0) g_cnt[b][regidx] = cnt;
        float* yp = Ps;  // reuse shared
        yp[w * 32 + lane] = acc;
        __syncthreads();
        if ((w & 3) == 0) {
            float sacc = g_xw[b][0][(size_t)row * FF + lane];
            #pragma unroll
            for (int ww = 0; ww < 4; ww++) sacc += yp[(w + ww) * 32 + lane];
            g_y[b][(size_t)row * FF + lane] = sacc;
        }
    }
}

// ---------------- K2b: deterministic column sums of y ----------------
__global__ void k_colsum() {
    int b = blockIdx.x;
    int col = threadIdx.x & 31, g = threadIdx.x >> 5;
    float acc = 0.f;
    for (int r = g; r < NN; r += 32) acc += g_y[b][r * FF + col];
    __shared__ float s[32][32];
    s[g][col] = acc;
    __syncthreads();
    if (g == 0) {
        float t = 0.f;
        #pragma unroll
        for (int gg = 0; gg < 32; gg++) t += s[gg][col];
        g_ysum[b][col] = t;
    }
}

// ---------------- K3: both branches' softmax-gather, one block per row ----------------
__global__ void k_attn(float* __restrict__ out) {
    int i = blockIdx.x;
    int w = threadIdx.x >> 5, lane = threadIdx.x & 31;
    __shared__ float sm[4], sl[4], sz[4][FF];
    const float NEGINF = __int_as_float(0xff800000u);
    float val = 0.f;

    for (int b = 0; b < 2; b++) {
        float s1i = g_s1[b][i];
        const float* __restrict__ s2 = g_s2[b];
        const float* __restrict__ y = g_y[b];
        int cnt = g_cnt[b][i * 4 + w];
        const u16* __restrict__ nz = &g_nzj[b][(size_t)(i * 4 + w) * CAPR];

        float mloc = NEGINF;
        for (int p = lane; p < cnt; p += 32) {
            float e = s1i + s2[nz[p]];
            float ev = e > 0.f ? e : NEG_SLOPE * e;
            mloc = fmaxf(mloc, ev);
        }
        #pragma unroll
        for (int d = 16; d; d >>= 1) mloc = fmaxf(mloc, __shfl_xor_sync(0xffffffffu, mloc, d));
        if (lane == 0) sm[w] = mloc;
        __syncthreads();
        float M = fmaxf(fmaxf(sm[0], sm[1]), fmaxf(sm[2], sm[3]));

        float l = 0.f, z = 0.f;
        if (M != NEGINF) {
            for (int p = 0; p < cnt; p++) {
                int j = nz[p];
                float e = s1i + s2[j];
                float ev = e > 0.f ? e : NEG_SLOPE * e;
                float pw = __expf(ev - M);
                l += pw;
                z += pw * y[(size_t)j * FF + lane];
            }
        }
        if (lane == 0) sl[w] = l;
        sz[w][lane] = z;
        __syncthreads();
        float bval;
        if (M == NEGINF) {
            bval = g_ysum[b][lane] * (1.f / NN);   // fully-masked row: uniform softmax
        } else {
            float Ltot = sl[0] + sl[1] + sl[2] + sl[3];
            float Z = sz[0][lane] + sz[1][lane] + sz[2][lane] + sz[3][lane];
            bval = Z / Ltot;
        }
        val += bval;
        __syncthreads();
    }
    if (w == 0) out[i * FF + lane] = val;
}

// ---------------- K5: out += sum of k-split partials (fixed order) ----------------
__global__ void k_final(float* __restrict__ out) {
    int idx = blockIdx.x * blockDim.x + threadIdx.x;
    float4 o = reinterpret_cast<float4*>(out)[idx];
    #pragma unroll
    for (int s = 0; s < KSPLIT; s++) {
        float4 p = reinterpret_cast<const float4*>(g_part[s])[idx];
        o.x += p.x; o.y += p.y; o.z += p.z; o.w += p.w;
    }
    reinterpret_cast<float4*>(out)[idx] = o;
}

extern "C" void kernel_launch(void* const* d_in, const int* in_sizes, int n_in,
                              void* d_out, int out_size) {
    const float* x    = (const float*)d_in[0];
    const float* Ld   = (const float*)d_in[1];
    const float* Lu   = (const float*)d_in[2];
    const float* P    = (const float*)d_in[3];
    const float* W1   = (const float*)d_in[4];
    const float* W2   = (const float*)d_in[5];
    const float* W0   = (const float*)d_in[6];
    const float* att1 = (const float*)d_in[7];
    const float* att2 = (const float*)d_in[8];
    float* out = (float*)d_out;

    k_pre<<<NN / 4, 128>>>(x, W1, W2, W0, att1, att2);
    k_mid<<<PGB + 2 * 2048, 256>>>(P, Ld, Lu);
    k_colsum<<<2, 1024>>>();
    k_attn<<<NN, 128>>>(out);
    k_final<<<NN * FF / 4 / 256, 256>>>(out);
}

// round 4
// speedup vs baseline: 1.3094x; 1.1668x over previous
#include <cuda_runtime.h>
#include <cstdint>

typedef unsigned long long ull;
typedef unsigned short u16;

#define NN 4096
#define FF 32
#define NEG_SLOPE 0.2f
#define CAPR 64
#define KSPLIT 8
#define RP 264

__device__ float g_xw[2][2][NN * FF];
__device__ float g_xw0[NN * FF];
__device__ float g_s1[2][NN];
__device__ float g_s2[2][NN];
__device__ float g_y[2][NN * FF];
__device__ float g_ysp[2][32][FF];        // colsum partials
__device__ u16   g_nzj[2][(size_t)NN * 4 * CAPR];
__device__ int   g_cnt[2][NN * 4];
__device__ float g_part[KSPLIT][NN * FF];

__device__ __forceinline__ ull ffma2(ull a, ull b, ull c) {
    ull d;
    asm("fma.rn.f32x2 %0, %1, %2, %3;" : "=l"(d) : "l"(a), "l"(b), "l"(c));
    return d;
}
__device__ __forceinline__ ull pack2(float lo, float hi) {
    ull d;
    asm("mov.b64 %0, {%1, %2};" : "=l"(d) : "f"(lo), "f"(hi));
    return d;
}
__device__ __forceinline__ float2 unpack2(ull v) {
    float2 r;
    asm("mov.b64 {%0, %1}, %2;" : "=f"(r.x), "=f"(r.y) : "l"(v));
    return r;
}
__device__ __forceinline__ float warp_sum(float p) {
    #pragma unroll
    for (int d = 16; d; d >>= 1) p += __shfl_xor_sync(0xffffffffu, p, d);
    return p;
}

// ---------------- K1: xw[k] = x@W[k], xw0 = x@W0, s1/s2 vectors ----------------
__global__ void k_pre(const float* __restrict__ x, const float* __restrict__ W1,
                      const float* __restrict__ W2, const float* __restrict__ W0,
                      const float* __restrict__ att1, const float* __restrict__ att2) {
    int w = threadIdx.x >> 5, lane = threadIdx.x & 31;
    int i = blockIdx.x * 4 + w;
    float xv = x[i * FF + lane];

    float o0 = 0.f, o1 = 0.f, o2 = 0.f, o3 = 0.f, o4 = 0.f;
    #pragma unroll
    for (int f = 0; f < FF; f++) {
        float xf = __shfl_sync(0xffffffffu, xv, f);
        o0 += xf * __ldg(&W1[f * FF + lane]);
        o1 += xf * __ldg(&W1[1024 + f * FF + lane]);
        o2 += xf * __ldg(&W2[f * FF + lane]);
        o3 += xf * __ldg(&W2[1024 + f * FF + lane]);
        o4 += xf * __ldg(&W0[f * FF + lane]);
    }
    g_xw[0][0][i * FF + lane] = o0;
    g_xw[0][1][i * FF + lane] = o1;
    g_xw[1][0][i * FF + lane] = o2;
    g_xw[1][1][i * FF + lane] = o3;
    g_xw0[i * FF + lane] = o4;

    float p;
    p = warp_sum(o0 * __ldg(&att1[lane]) + o1 * __ldg(&att1[FF + lane]));
    if (lane == 0) g_s1[0][i] = p;
    p = warp_sum(o0 * __ldg(&att1[2 * FF + lane]) + o1 * __ldg(&att1[3 * FF + lane]));
    if (lane == 0) g_s2[0][i] = p;
    p = warp_sum(o2 * __ldg(&att2[lane]) + o3 * __ldg(&att2[FF + lane]));
    if (lane == 0) g_s1[1][i] = p;
    p = warp_sum(o2 * __ldg(&att2[2 * FF + lane]) + o3 * __ldg(&att2[3 * FF + lane]));
    if (lane == 0) g_s2[1][i] = p;
}

// ---------------- K2: P-GEMM, col-pair f32x2, BM=256, KSPLIT=8 ----------------
__global__ __launch_bounds__(256) void k_pgemm(const float* __restrict__ P) {
    __shared__ __align__(16) float Ps[32 * RP];   // [k][row ^ swizzle]
    __shared__ __align__(16) float Bs[32 * FF];   // [k][col] natural

    int rb = blockIdx.x * 256, k0 = blockIdx.y * 512;
    int t = threadIdx.x;
    int c4 = t & 7, row0 = t >> 3;     // loader mapping
    int colg = t & 7, rowg = t >> 3;   // compute: rows rowg*8..+7, cols colg*4..+3

    const float4* __restrict__ P4 = (const float4*)P;
    const float4* __restrict__ B4 = (const float4*)g_xw0;

    ull acc[8][2];
    #pragma unroll
    for (int i = 0; i < 8; i++) { acc[i][0] = 0ull; acc[i][1] = 0ull; }

    float4 pv[8]; float4 bv;
    {
        #pragma unroll
        for (int it = 0; it < 8; it++)
            pv[it] = P4[(size_t)(rb + row0 + it * 32) * (NN / 4) + (k0 >> 2) + c4];
        bv = B4[(size_t)(k0 + row0) * (FF / 4) + c4];
    }
    for (int kt = 0; kt < 16; kt++) {
        int sw = (c4 & 3) << 3;
        #pragma unroll
        for (int it = 0; it < 8; it++) {
            int r = (row0 ^ sw) + it * 32;
            Ps[(4 * c4 + 0) * RP + r] = pv[it].x;
            Ps[(4 * c4 + 1) * RP + r] = pv[it].y;
            Ps[(4 * c4 + 2) * RP + r] = pv[it].z;
            Ps[(4 * c4 + 3) * RP + r] = pv[it].w;
        }
        ((float4*)Bs)[row0 * (FF / 4) + c4] = bv;
        __syncthreads();
        if (kt < 15) {
            int kk = k0 + (kt + 1) * 32;
            #pragma unroll
            for (int it = 0; it < 8; it++)
                pv[it] = P4[(size_t)(rb + row0 + it * 32) * (NN / 4) + (kk >> 2) + c4];
            bv = B4[(size_t)(kk + row0) * (FF / 4) + c4];
        }
        #pragma unroll
        for (int k = 0; k < 32; k++) {
            int swk = ((k >> 2) & 3) << 3;
            const float* pr = &Ps[k * RP + ((rowg * 8) ^ swk)];
            float4 pa = *(const float4*)pr;
            float4 pb = *(const float4*)(pr + 4);
            float4 b = *(const float4*)&Bs[k * FF + colg * 4];
            ull b01 = pack2(b.x, b.y);
            ull b23 = pack2(b.z, b.w);
            float pe[8] = {pa.x, pa.y, pa.z, pa.w, pb.x, pb.y, pb.z, pb.w};
            #pragma unroll
            for (int i = 0; i < 8; i++) {
                ull pd = pack2(pe[i], pe[i]);
                acc[i][0] = ffma2(pd, b01, acc[i][0]);
                acc[i][1] = ffma2(pd, b23, acc[i][1]);
            }
        }
        __syncthreads();
    }
    float* __restrict__ outp = g_part[blockIdx.y];
    int c0 = colg * 4;
    #pragma unroll
    for (int i = 0; i < 8; i++) {
        float2 f0 = unpack2(acc[i][0]);
        float2 f1 = unpack2(acc[i][1]);
        float4 o = make_float4(f0.x, f0.y, f1.x, f1.y);
        *(float4*)&outp[(size_t)(rb + rowg * 8 + i) * FF + c0] = o;
    }
}

// ---------------- K3: SpMM y = xw0 + L@xw1 + nz list build; grid (2048, 2) ----------------
__global__ __launch_bounds__(256) void k_spmm(const float* __restrict__ Ld,
                                              const float* __restrict__ Lu) {
    int b = blockIdx.y;
    int t = threadIdx.x;
    int w = t >> 5, lane = t & 31;
    int row = (blockIdx.x << 1) + (w >> 2);
    int r = w & 3;
    const float* __restrict__ L = b ? Lu : Ld;
    const float4* __restrict__ Lr4 = (const float4*)(L + (size_t)row * NN + r * 1024);

    float4 v[8];
    #pragma unroll
    for (int it = 0; it < 8; it++) v[it] = Lr4[it * 32 + lane];

    const float* __restrict__ xw1 = g_xw[b][1];
    int regidx = row * 4 + r;
    u16* __restrict__ nz = &g_nzj[b][(size_t)regidx * CAPR];
    int cbase = r * 1024;
    int cnt = 0; float acc = 0.f;
    #pragma unroll
    for (int it = 0; it < 8; it++) {
        float4 q = v[it];
        bool any = (q.x != 0.f) || (q.y != 0.f) || (q.z != 0.f) || (q.w != 0.f);
        unsigned mask = __ballot_sync(0xffffffffu, any);
        while (mask) {
            int s = __ffs(mask) - 1; mask &= mask - 1;
            float u0 = __shfl_sync(0xffffffffu, q.x, s);
            float u1 = __shfl_sync(0xffffffffu, q.y, s);
            float u2 = __shfl_sync(0xffffffffu, q.z, s);
            float u3 = __shfl_sync(0xffffffffu, q.w, s);
            int col0 = cbase + it * 128 + s * 4;
            float uv[4] = {u0, u1, u2, u3};
            #pragma unroll
            for (int e = 0; e < 4; e++) {
                if (uv[e] != 0.f) {   // warp-uniform
                    acc += uv[e] * xw1[(size_t)(col0 + e) * FF + lane];
                    if (lane == 0 && cnt < CAPR) nz[cnt] = (u16)(col0 + e);
                    cnt++;
                }
            }
        }
    }
    if (cnt > CAPR) cnt = CAPR;
    if (lane == 0) g_cnt[b][regidx] = cnt;

    __shared__ float yp[8][FF];
    yp[w][lane] = acc;
    __syncthreads();
    if ((w & 3) == 0) {
        float s = g_xw[b][0][(size_t)row * FF + lane];
        #pragma unroll
        for (int ww = 0; ww < 4; ww++) s += yp[(w & 4) + ww][lane];
        g_y[b][(size_t)row * FF + lane] = s;
    }
}

// ---------------- K3b: colsum partials of y; grid (32, 2) ----------------
__global__ void k_colsum(void) {
    int b = blockIdx.y, chunk = blockIdx.x;
    int w = threadIdx.x >> 5, lane = threadIdx.x & 31;
    float acc = 0.f;
    int r0 = chunk * 128 + w * 16;
    #pragma unroll
    for (int i = 0; i < 16; i++) acc += g_y[b][(size_t)(r0 + i) * FF + lane];
    __shared__ float s[8][FF];
    s[w][lane] = acc;
    __syncthreads();
    if (w == 0) {
        float t = 0.f;
        #pragma unroll
        for (int ww = 0; ww < 8; ww++) t += s[ww][lane];
        g_ysp[b][chunk][lane] = t;
    }
}

// ---------------- K4: attention, one warp per row, both branches ----------------
__global__ void k_attn(float* __restrict__ out) {
    int i = blockIdx.x * 8 + (threadIdx.x >> 5);
    int lane = threadIdx.x & 31;
    const float NEGINF = __int_as_float(0xff800000u);
    float val = 0.f;

    #pragma unroll
    for (int b = 0; b < 2; b++) {
        float s1i = g_s1[b][i];
        const float* __restrict__ s2 = g_s2[b];
        const float* __restrict__ y = g_y[b];
        const int* __restrict__ cp = &g_cnt[b][i * 4];
        int c0 = cp[0], c1 = cp[1], c2 = cp[2], c3 = cp[3];
        int cnts[4] = {c0, c1, c2, c3};
        int tot = c0 + c1 + c2 + c3;

        if (tot == 0) {
            float t = 0.f;
            #pragma unroll
            for (int p = 0; p < 32; p++) t += g_ysp[b][p][lane];
            val += t * (1.f / NN);
            continue;
        }
        // pass A: max of s2 over nz (leakyrelu monotone => M = lrelu(s1i + max s2))
        float mx = NEGINF;
        #pragma unroll
        for (int r = 0; r < 4; r++) {
            const u16* __restrict__ nz = &g_nzj[b][(size_t)(i * 4 + r) * CAPR];
            for (int p = lane; p < cnts[r]; p += 32) mx = fmaxf(mx, s2[nz[p]]);
        }
        #pragma unroll
        for (int d = 16; d; d >>= 1) mx = fmaxf(mx, __shfl_xor_sync(0xffffffffu, mx, d));
        float eM = s1i + mx;
        float M = eM > 0.f ? eM : NEG_SLOPE * eM;

        float l = 0.f, z = 0.f;
        #pragma unroll
        for (int r = 0; r < 4; r++) {
            const u16* __restrict__ nz = &g_nzj[b][(size_t)(i * 4 + r) * CAPR];
            int c = cnts[r];
            for (int p = 0; p < c; p++) {
                int j = nz[p];
                float e = s1i + s2[j];
                float ev = e > 0.f ? e : NEG_SLOPE * e;
                float pw = __expf(ev - M);
                l += pw;
                z += pw * y[(size_t)j * FF + lane];
            }
        }
        val += z / l;
    }
    out[(size_t)i * FF + lane] = val;
}

// ---------------- K5: out += sum of k-split partials (fixed order) ----------------
__global__ void k_final(float* __restrict__ out) {
    int idx = blockIdx.x * blockDim.x + threadIdx.x;
    float4 o = reinterpret_cast<float4*>(out)[idx];
    #pragma unroll
    for (int s = 0; s < KSPLIT; s++) {
        float4 p = reinterpret_cast<const float4*>(g_part[s])[idx];
        o.x += p.x; o.y += p.y; o.z += p.z; o.w += p.w;
    }
    reinterpret_cast<float4*>(out)[idx] = o;
}

extern "C" void kernel_launch(void* const* d_in, const int* in_sizes, int n_in,
                              void* d_out, int out_size) {
    const float* x    = (const float*)d_in[0];
    const float* Ld   = (const float*)d_in[1];
    const float* Lu   = (const float*)d_in[2];
    const float* P    = (const float*)d_in[3];
    const float* W1   = (const float*)d_in[4];
    const float* W2   = (const float*)d_in[5];
    const float* W0   = (const float*)d_in[6];
    const float* att1 = (const float*)d_in[7];
    const float* att2 = (const float*)d_in[8];
    float* out = (float*)d_out;

    k_pre<<<NN / 4, 128>>>(x, W1, W2, W0, att1, att2);
    k_pgemm<<<dim3(16, KSPLIT), 256>>>(P);
    k_spmm<<<dim3(2048, 2), 256>>>(Ld, Lu);
    k_colsum<<<dim3(32, 2), 256>>>();
    k_attn<<<512, 256>>>(out);
    k_final<<<NN * FF / 4 / 256, 256>>>(out);
}

// round 5
// speedup vs baseline: 1.5249x; 1.1646x over previous
#include <cuda_runtime.h>
#include <cstdint>

typedef unsigned long long ull;
typedef unsigned short u16;

#define NN 4096
#define FF 32
#define NEG_SLOPE 0.2f
#define CAPR 128
#define KSPLIT 16
#define RP 520
#define PGSMEM (32 * RP * 4 + 32 * 40 * 8)

__device__ float g_xw[2][2][NN * FF];
__device__ float g_xw0[NN * FF];
__device__ float g_s1[2][NN];
__device__ float g_s2[2][NN];
__device__ float g_y[2][NN * FF];
__device__ u16   g_nzj[2][(size_t)NN * 4 * CAPR];
__device__ int   g_cnt[2][NN * 4];
__device__ float g_part[KSPLIT][NN * FF];

__device__ __forceinline__ ull ffma2(ull a, ull b, ull c) {
    ull d;
    asm("fma.rn.f32x2 %0, %1, %2, %3;" : "=l"(d) : "l"(a), "l"(b), "l"(c));
    return d;
}
__device__ __forceinline__ ull pack2(float lo, float hi) {
    ull d;
    asm("mov.b64 %0, {%1, %2};" : "=l"(d) : "f"(lo), "f"(hi));
    return d;
}
__device__ __forceinline__ float2 unpack2(ull v) {
    float2 r;
    asm("mov.b64 {%0, %1}, %2;" : "=f"(r.x), "=f"(r.y) : "l"(v));
    return r;
}
__device__ __forceinline__ float warp_sum(float p) {
    #pragma unroll
    for (int d = 16; d; d >>= 1) p += __shfl_xor_sync(0xffffffffu, p, d);
    return p;
}

// ---------------- K1: xw[k] = x@W[k], xw0 = x@W0, s1/s2 vectors ----------------
__global__ void k_pre(const float* __restrict__ x, const float* __restrict__ W1,
                      const float* __restrict__ W2, const float* __restrict__ W0,
                      const float* __restrict__ att1, const float* __restrict__ att2) {
    int w = threadIdx.x >> 5, lane = threadIdx.x & 31;
    int i = blockIdx.x * 4 + w;
    float xv = x[i * FF + lane];

    float o0 = 0.f, o1 = 0.f, o2 = 0.f, o3 = 0.f, o4 = 0.f;
    #pragma unroll
    for (int f = 0; f < FF; f++) {
        float xf = __shfl_sync(0xffffffffu, xv, f);
        o0 += xf * __ldg(&W1[f * FF + lane]);
        o1 += xf * __ldg(&W1[1024 + f * FF + lane]);
        o2 += xf * __ldg(&W2[f * FF + lane]);
        o3 += xf * __ldg(&W2[1024 + f * FF + lane]);
        o4 += xf * __ldg(&W0[f * FF + lane]);
    }
    g_xw[0][0][i * FF + lane] = o0;
    g_xw[0][1][i * FF + lane] = o1;
    g_xw[1][0][i * FF + lane] = o2;
    g_xw[1][1][i * FF + lane] = o3;
    g_xw0[i * FF + lane] = o4;

    float p;
    p = warp_sum(o0 * __ldg(&att1[lane]) + o1 * __ldg(&att1[FF + lane]));
    if (lane == 0) g_s1[0][i] = p;
    p = warp_sum(o0 * __ldg(&att1[2 * FF + lane]) + o1 * __ldg(&att1[3 * FF + lane]));
    if (lane == 0) g_s2[0][i] = p;
    p = warp_sum(o2 * __ldg(&att2[lane]) + o3 * __ldg(&att2[FF + lane]));
    if (lane == 0) g_s1[1][i] = p;
    p = warp_sum(o2 * __ldg(&att2[2 * FF + lane]) + o3 * __ldg(&att2[3 * FF + lane]));
    if (lane == 0) g_s2[1][i] = p;
}

// ---------------- K2: P-GEMM  BM=512, 8x8 thread tile, f32x2, KSPLIT=16 ----------------
// Layout: Ps float at [k*520 + (row ^ sw2(k>>2) ^ ((row>>5 & 7)<<2))]
//         Bs dup ull  at [k*40 + (col>>3)*10 + (col&7)]
__global__ __launch_bounds__(256, 1) void k_pgemm(const float* __restrict__ P) {
    extern __shared__ __align__(16) unsigned char smraw[];
    float* Ps = (float*)smraw;
    ull*   Bs = (ull*)(smraw + 32 * RP * 4);

    int t = threadIdx.x;
    int rb = blockIdx.x * 512, k0 = blockIdx.y * 256;
    // loader mapping
    int c4 = t & 7, row0 = t >> 3;
    int sw2c4 = ((c4 & 3) << 3) ^ ((c4 >> 2) << 2);
    // B loader mapping
    int kq = t >> 3, c4b = t & 7;
    int bbase = kq * 40 + (c4b >> 1) * 10 + (c4b & 1) * 4;
    // compute mapping
    int rowg = t >> 2, colg = t & 3;
    int rXor = ((rowg >> 2) & 7) << 2;

    const float4* __restrict__ P4 = (const float4*)P;
    const float4* __restrict__ B4 = (const float4*)g_xw0;

    ull acc[4][8];
    #pragma unroll
    for (int i = 0; i < 4; i++)
        #pragma unroll
        for (int j = 0; j < 8; j++) acc[i][j] = 0ull;

    float4 pv[16]; float4 bv;
    #pragma unroll
    for (int j = 0; j < 16; j++)
        pv[j] = P4[(size_t)(rb + row0 + 32 * j) * (NN / 4) + (k0 >> 2) + c4];
    bv = B4[(size_t)(k0 + kq) * (FF / 4) + c4b];

    for (int kt = 0; kt < 8; kt++) {
        __syncthreads();
        #pragma unroll
        for (int j = 0; j < 16; j++) {
            int X = sw2c4 ^ ((j & 7) << 2);
            int rbase = 32 * j + (row0 ^ X);
            Ps[(4 * c4 + 0) * RP + rbase] = pv[j].x;
            Ps[(4 * c4 + 1) * RP + rbase] = pv[j].y;
            Ps[(4 * c4 + 2) * RP + rbase] = pv[j].z;
            Ps[(4 * c4 + 3) * RP + rbase] = pv[j].w;
        }
        Bs[bbase + 0] = pack2(bv.x, bv.x);
        Bs[bbase + 1] = pack2(bv.y, bv.y);
        Bs[bbase + 2] = pack2(bv.z, bv.z);
        Bs[bbase + 3] = pack2(bv.w, bv.w);
        __syncthreads();
        if (kt < 7) {
            int kk = k0 + (kt + 1) * 32;
            #pragma unroll
            for (int j = 0; j < 16; j++)
                pv[j] = P4[(size_t)(rb + row0 + 32 * j) * (NN / 4) + (kk >> 2) + c4];
            bv = B4[(size_t)(kk + kq) * (FF / 4) + c4b];
        }
        #pragma unroll
        for (int k = 0; k < 32; k++) {
            int c4k = k >> 2;
            int XA = (((c4k & 3) << 3) ^ ((c4k >> 2) << 2)) ^ rXor;
            const ulonglong2 pA = *(const ulonglong2*)&Ps[k * RP + ((rowg * 8) ^ XA)];
            const ulonglong2 pB = *(const ulonglong2*)&Ps[k * RP + ((rowg * 8 + 4) ^ XA)];
            const ull* bp = &Bs[k * 40 + colg * 10];
            const ulonglong2 b01 = *(const ulonglong2*)(bp + 0);
            const ulonglong2 b23 = *(const ulonglong2*)(bp + 2);
            const ulonglong2 b45 = *(const ulonglong2*)(bp + 4);
            const ulonglong2 b67 = *(const ulonglong2*)(bp + 6);
            ull pp[4] = {pA.x, pA.y, pB.x, pB.y};
            ull bbv[8] = {b01.x, b01.y, b23.x, b23.y, b45.x, b45.y, b67.x, b67.y};
            #pragma unroll
            for (int i = 0; i < 4; i++)
                #pragma unroll
                for (int j = 0; j < 8; j++)
                    acc[i][j] = ffma2(pp[i], bbv[j], acc[i][j]);
        }
    }
    float* __restrict__ outp = g_part[blockIdx.y];
    int r0 = rb + rowg * 8, c0 = colg * 8;
    #pragma unroll
    for (int rp = 0; rp < 4; rp++) {
        float2 f[8];
        #pragma unroll
        for (int c = 0; c < 8; c++) f[c] = unpack2(acc[rp][c]);
        float4 lo0 = make_float4(f[0].x, f[1].x, f[2].x, f[3].x);
        float4 lo1 = make_float4(f[4].x, f[5].x, f[6].x, f[7].x);
        float4 hi0 = make_float4(f[0].y, f[1].y, f[2].y, f[3].y);
        float4 hi1 = make_float4(f[4].y, f[5].y, f[6].y, f[7].y);
        *(float4*)&outp[(size_t)(r0 + 2 * rp) * FF + c0]         = lo0;
        *(float4*)&outp[(size_t)(r0 + 2 * rp) * FF + c0 + 4]     = lo1;
        *(float4*)&outp[(size_t)(r0 + 2 * rp + 1) * FF + c0]     = hi0;
        *(float4*)&outp[(size_t)(r0 + 2 * rp + 1) * FF + c0 + 4] = hi1;
    }
}

// ---------------- K3: SpMM two-phase; grid (2048, 2) ----------------
__global__ __launch_bounds__(256) void k_spmm(const float* __restrict__ Ld,
                                              const float* __restrict__ Lu) {
    __shared__ float4 qv[8][64];
    __shared__ u16    qs[8][64];
    __shared__ float  yp[8][FF];
    int b = blockIdx.y;
    int t = threadIdx.x;
    int w = t >> 5, lane = t & 31;
    int row = (blockIdx.x << 1) + (w >> 2);
    int r = w & 3;
    const float* __restrict__ L = b ? Lu : Ld;
    const float4* __restrict__ Lr4 = (const float4*)(L + (size_t)row * NN + r * 1024);

    float4 v[8];
    #pragma unroll
    for (int it = 0; it < 8; it++) v[it] = __ldcs(&Lr4[it * 32 + lane]);

    unsigned msk[8]; int tot = 0;
    #pragma unroll
    for (int it = 0; it < 8; it++) {
        float4 q = v[it];
        bool any = (q.x != 0.f) || (q.y != 0.f) || (q.z != 0.f) || (q.w != 0.f);
        msk[it] = __ballot_sync(0xffffffffu, any);
        tot += __popc(msk[it]);
    }

    const float* __restrict__ xw1 = g_xw[b][1];
    int regidx = row * 4 + r;
    u16* __restrict__ nz = &g_nzj[b][(size_t)regidx * CAPR];
    int cbase = r * 1024;
    float acc0 = 0.f, acc1 = 0.f;
    int nzc = 0;

    if (tot <= 64) {
        int cnt = 0;
        #pragma unroll
        for (int it = 0; it < 8; it++) {
            unsigned m = msk[it];
            if ((m >> lane) & 1u) {
                int pos = cnt + __popc(m & ((1u << lane) - 1u));
                qv[w][pos] = v[it];
                qs[w][pos] = (u16)(it * 32 + lane);
            }
            cnt += __popc(m);
        }
        __syncwarp();
        for (int p = 0; p < cnt; p++) {
            float4 q = qv[w][p];
            int col0 = cbase + ((int)qs[w][p]) * 4;
            if (q.x != 0.f) { acc0 += q.x * xw1[(size_t)(col0 + 0) * FF + lane];
                              if (lane == 0 && nzc < CAPR) nz[nzc] = (u16)(col0 + 0); nzc++; }
            if (q.y != 0.f) { acc1 += q.y * xw1[(size_t)(col0 + 1) * FF + lane];
                              if (lane == 0 && nzc < CAPR) nz[nzc] = (u16)(col0 + 1); nzc++; }
            if (q.z != 0.f) { acc0 += q.z * xw1[(size_t)(col0 + 2) * FF + lane];
                              if (lane == 0 && nzc < CAPR) nz[nzc] = (u16)(col0 + 2); nzc++; }
            if (q.w != 0.f) { acc1 += q.w * xw1[(size_t)(col0 + 3) * FF + lane];
                              if (lane == 0 && nzc < CAPR) nz[nzc] = (u16)(col0 + 3); nzc++; }
        }
    } else {
        #pragma unroll
        for (int it = 0; it < 8; it++) {
            float4 q = v[it];
            unsigned mask = msk[it];
            while (mask) {
                int s = __ffs(mask) - 1; mask &= mask - 1;
                float u0 = __shfl_sync(0xffffffffu, q.x, s);
                float u1 = __shfl_sync(0xffffffffu, q.y, s);
                float u2 = __shfl_sync(0xffffffffu, q.z, s);
                float u3 = __shfl_sync(0xffffffffu, q.w, s);
                int col0 = cbase + it * 128 + s * 4;
                float uv[4] = {u0, u1, u2, u3};
                #pragma unroll
                for (int e = 0; e < 4; e++) {
                    if (uv[e] != 0.f) {
                        acc0 += uv[e] * xw1[(size_t)(col0 + e) * FF + lane];
                        if (lane == 0 && nzc < CAPR) nz[nzc] = (u16)(col0 + e);
                        nzc++;
                    }
                }
            }
        }
    }
    if (lane == 0) g_cnt[b][regidx] = (nzc < CAPR) ? nzc : CAPR;

    yp[w][lane] = acc0 + acc1;
    __syncthreads();
    if ((w & 3) == 0) {
        float s = g_xw[b][0][(size_t)row * FF + lane];
        #pragma unroll
        for (int ww = 0; ww < 4; ww++) s += yp[(w & 4) + ww][lane];
        g_y[b][(size_t)row * FF + lane] = s;
    }
}

// ---------------- K4: attention (warp per row) + fold in pgemm partial reduce ----------------
__global__ void k_attn(float* __restrict__ out) {
    int i = blockIdx.x * 8 + (threadIdx.x >> 5);
    int lane = threadIdx.x & 31;
    const float NEGINF = __int_as_float(0xff800000u);

    float val = 0.f;
    #pragma unroll
    for (int s = 0; s < KSPLIT; s++) val += g_part[s][(size_t)i * FF + lane];

    #pragma unroll
    for (int b = 0; b < 2; b++) {
        float s1i = g_s1[b][i];
        const float* __restrict__ s2 = g_s2[b];
        const float* __restrict__ y = g_y[b];
        int4 c4 = *(const int4*)&g_cnt[b][i * 4];
        int cnts[4] = {c4.x, c4.y, c4.z, c4.w};
        int tot = c4.x + c4.y + c4.z + c4.w;

        if (tot == 0) {   // fully-masked row: uniform softmax (improbable; correctness path)
            float tsum = 0.f;
            for (int j = 0; j < NN; j++) tsum += y[(size_t)j * FF + lane];
            val += tsum * (1.f / NN);
            continue;
        }
        // pass A: max of s2 over nz (leakyrelu monotone)
        float mx = NEGINF;
        #pragma unroll
        for (int r = 0; r < 4; r++) {
            const u16* __restrict__ nzp = &g_nzj[b][(size_t)(i * 4 + r) * CAPR];
            for (int p = lane; p < cnts[r]; p += 32) mx = fmaxf(mx, s2[nzp[p]]);
        }
        #pragma unroll
        for (int d = 16; d; d >>= 1) mx = fmaxf(mx, __shfl_xor_sync(0xffffffffu, mx, d));
        float eM = s1i + mx;
        float M = eM > 0.f ? eM : NEG_SLOPE * eM;

        float l0 = 0.f, l1 = 0.f, z0 = 0.f, z1 = 0.f;
        #pragma unroll
        for (int r = 0; r < 4; r++) {
            const u16* __restrict__ nzp = &g_nzj[b][(size_t)(i * 4 + r) * CAPR];
            int c = cnts[r];
            int p = 0;
            for (; p + 1 < c; p += 2) {
                int j0 = nzp[p], j1 = nzp[p + 1];
                float e0 = s1i + s2[j0];
                float e1 = s1i + s2[j1];
                float ev0 = e0 > 0.f ? e0 : NEG_SLOPE * e0;
                float ev1 = e1 > 0.f ? e1 : NEG_SLOPE * e1;
                float pw0 = __expf(ev0 - M);
                float pw1 = __expf(ev1 - M);
                l0 += pw0; l1 += pw1;
                z0 += pw0 * y[(size_t)j0 * FF + lane];
                z1 += pw1 * y[(size_t)j1 * FF + lane];
            }
            if (p < c) {
                int j0 = nzp[p];
                float e0 = s1i + s2[j0];
                float ev0 = e0 > 0.f ? e0 : NEG_SLOPE * e0;
                float pw0 = __expf(ev0 - M);
                l0 += pw0;
                z0 += pw0 * y[(size_t)j0 * FF + lane];
            }
        }
        val += (z0 + z1) / (l0 + l1);
    }
    out[(size_t)i * FF + lane] = val;
}

extern "C" void kernel_launch(void* const* d_in, const int* in_sizes, int n_in,
                              void* d_out, int out_size) {
    const float* x    = (const float*)d_in[0];
    const float* Ld   = (const float*)d_in[1];
    const float* Lu   = (const float*)d_in[2];
    const float* P    = (const float*)d_in[3];
    const float* W1   = (const float*)d_in[4];
    const float* W2   = (const float*)d_in[5];
    const float* W0   = (const float*)d_in[6];
    const float* att1 = (const float*)d_in[7];
    const float* att2 = (const float*)d_in[8];
    float* out = (float*)d_out;

    cudaFuncSetAttribute(k_pgemm, cudaFuncAttributeMaxDynamicSharedMemorySize, PGSMEM);
    k_pre<<<NN / 4, 128>>>(x, W1, W2, W0, att1, att2);
    k_pgemm<<<dim3(NN / 512, KSPLIT), 256, PGSMEM>>>(P);
    k_spmm<<<dim3(2048, 2), 256>>>(Ld, Lu);
    k_attn<<<NN / 8, 256>>>(out);
}

// round 6
// speedup vs baseline: 1.5541x; 1.0191x over previous
#include <cuda_runtime.h>
#include <cstdint>

typedef unsigned long long ull;
typedef unsigned short u16;

#define NN 4096
#define FF 32
#define NEG_SLOPE 0.2f
#define CAPR 128
#define KSPLIT 16
#define RP 520
#define PGSMEM (32 * RP * 4 + 32 * 40 * 8)

__device__ float g_xw[2][2][NN * FF];
__device__ float g_xw0[NN * FF];
__device__ float g_s1[2][NN];
__device__ float g_s2[2][NN];
__device__ float g_y[2][NN * FF];
__device__ u16   g_nzj[2][(size_t)NN * 4 * CAPR];
__device__ int   g_cnt[2][NN * 4];
__device__ float g_part[KSPLIT][NN * FF];

__device__ __forceinline__ ull ffma2(ull a, ull b, ull c) {
    ull d;
    asm("fma.rn.f32x2 %0, %1, %2, %3;" : "=l"(d) : "l"(a), "l"(b), "l"(c));
    return d;
}
__device__ __forceinline__ ull pack2(float lo, float hi) {
    ull d;
    asm("mov.b64 %0, {%1, %2};" : "=l"(d) : "f"(lo), "f"(hi));
    return d;
}
__device__ __forceinline__ float2 unpack2(ull v) {
    float2 r;
    asm("mov.b64 {%0, %1}, %2;" : "=f"(r.x), "=f"(r.y) : "l"(v));
    return r;
}
__device__ __forceinline__ float warp_sum(float p) {
    #pragma unroll
    for (int d = 16; d; d >>= 1) p += __shfl_xor_sync(0xffffffffu, p, d);
    return p;
}
__device__ __forceinline__ float lrelu(float e) {
    return e > 0.f ? e : NEG_SLOPE * e;
}

// ---------------- K1: xw[k] = x@W[k], xw0 = x@W0, s1/s2 vectors ----------------
__global__ void k_pre(const float* __restrict__ x, const float* __restrict__ W1,
                      const float* __restrict__ W2, const float* __restrict__ W0,
                      const float* __restrict__ att1, const float* __restrict__ att2) {
    int w = threadIdx.x >> 5, lane = threadIdx.x & 31;
    int i = blockIdx.x * 4 + w;
    float xv = x[i * FF + lane];

    float o0 = 0.f, o1 = 0.f, o2 = 0.f, o3 = 0.f, o4 = 0.f;
    #pragma unroll
    for (int f = 0; f < FF; f++) {
        float xf = __shfl_sync(0xffffffffu, xv, f);
        o0 += xf * __ldg(&W1[f * FF + lane]);
        o1 += xf * __ldg(&W1[1024 + f * FF + lane]);
        o2 += xf * __ldg(&W2[f * FF + lane]);
        o3 += xf * __ldg(&W2[1024 + f * FF + lane]);
        o4 += xf * __ldg(&W0[f * FF + lane]);
    }
    g_xw[0][0][i * FF + lane] = o0;
    g_xw[0][1][i * FF + lane] = o1;
    g_xw[1][0][i * FF + lane] = o2;
    g_xw[1][1][i * FF + lane] = o3;
    g_xw0[i * FF + lane] = o4;

    float p;
    p = warp_sum(o0 * __ldg(&att1[lane]) + o1 * __ldg(&att1[FF + lane]));
    if (lane == 0) g_s1[0][i] = p;
    p = warp_sum(o0 * __ldg(&att1[2 * FF + lane]) + o1 * __ldg(&att1[3 * FF + lane]));
    if (lane == 0) g_s2[0][i] = p;
    p = warp_sum(o2 * __ldg(&att2[lane]) + o3 * __ldg(&att2[FF + lane]));
    if (lane == 0) g_s1[1][i] = p;
    p = warp_sum(o2 * __ldg(&att2[2 * FF + lane]) + o3 * __ldg(&att2[3 * FF + lane]));
    if (lane == 0) g_s2[1][i] = p;
}

// ---------------- K2: P-GEMM  BM=512, 8x8 thread tile, f32x2, KSPLIT=16 ----------------
__global__ __launch_bounds__(256, 1) void k_pgemm(const float* __restrict__ P) {
    extern __shared__ __align__(16) unsigned char smraw[];
    float* Ps = (float*)smraw;
    ull*   Bs = (ull*)(smraw + 32 * RP * 4);

    int t = threadIdx.x;
    int rb = blockIdx.x * 512, k0 = blockIdx.y * 256;
    int c4 = t & 7, row0 = t >> 3;
    int sw2c4 = ((c4 & 3) << 3) ^ ((c4 >> 2) << 2);
    int kq = t >> 3, c4b = t & 7;
    int bbase = kq * 40 + (c4b >> 1) * 10 + (c4b & 1) * 4;
    int rowg = t >> 2, colg = t & 3;
    int rXor = ((rowg >> 2) & 7) << 2;

    const float4* __restrict__ P4 = (const float4*)P;
    const float4* __restrict__ B4 = (const float4*)g_xw0;

    ull acc[4][8];
    #pragma unroll
    for (int i = 0; i < 4; i++)
        #pragma unroll
        for (int j = 0; j < 8; j++) acc[i][j] = 0ull;

    float4 pv[16]; float4 bv;
    #pragma unroll
    for (int j = 0; j < 16; j++)
        pv[j] = P4[(size_t)(rb + row0 + 32 * j) * (NN / 4) + (k0 >> 2) + c4];
    bv = B4[(size_t)(k0 + kq) * (FF / 4) + c4b];

    for (int kt = 0; kt < 8; kt++) {
        __syncthreads();
        #pragma unroll
        for (int j = 0; j < 16; j++) {
            int X = sw2c4 ^ ((j & 7) << 2);
            int rbase = 32 * j + (row0 ^ X);
            Ps[(4 * c4 + 0) * RP + rbase] = pv[j].x;
            Ps[(4 * c4 + 1) * RP + rbase] = pv[j].y;
            Ps[(4 * c4 + 2) * RP + rbase] = pv[j].z;
            Ps[(4 * c4 + 3) * RP + rbase] = pv[j].w;
        }
        Bs[bbase + 0] = pack2(bv.x, bv.x);
        Bs[bbase + 1] = pack2(bv.y, bv.y);
        Bs[bbase + 2] = pack2(bv.z, bv.z);
        Bs[bbase + 3] = pack2(bv.w, bv.w);
        __syncthreads();
        if (kt < 7) {
            int kk = k0 + (kt + 1) * 32;
            #pragma unroll
            for (int j = 0; j < 16; j++)
                pv[j] = P4[(size_t)(rb + row0 + 32 * j) * (NN / 4) + (kk >> 2) + c4];
            bv = B4[(size_t)(kk + kq) * (FF / 4) + c4b];
        }
        #pragma unroll
        for (int k = 0; k < 32; k++) {
            int c4k = k >> 2;
            int XA = (((c4k & 3) << 3) ^ ((c4k >> 2) << 2)) ^ rXor;
            const ulonglong2 pA = *(const ulonglong2*)&Ps[k * RP + ((rowg * 8) ^ XA)];
            const ulonglong2 pB = *(const ulonglong2*)&Ps[k * RP + ((rowg * 8 + 4) ^ XA)];
            const ull* bp = &Bs[k * 40 + colg * 10];
            const ulonglong2 b01 = *(const ulonglong2*)(bp + 0);
            const ulonglong2 b23 = *(const ulonglong2*)(bp + 2);
            const ulonglong2 b45 = *(const ulonglong2*)(bp + 4);
            const ulonglong2 b67 = *(const ulonglong2*)(bp + 6);
            ull pp[4] = {pA.x, pA.y, pB.x, pB.y};
            ull bbv[8] = {b01.x, b01.y, b23.x, b23.y, b45.x, b45.y, b67.x, b67.y};
            #pragma unroll
            for (int i = 0; i < 4; i++)
                #pragma unroll
                for (int j = 0; j < 8; j++)
                    acc[i][j] = ffma2(pp[i], bbv[j], acc[i][j]);
        }
    }
    float* __restrict__ outp = g_part[blockIdx.y];
    int r0 = rb + rowg * 8, c0 = colg * 8;
    #pragma unroll
    for (int rp = 0; rp < 4; rp++) {
        float2 f[8];
        #pragma unroll
        for (int c = 0; c < 8; c++) f[c] = unpack2(acc[rp][c]);
        float4 lo0 = make_float4(f[0].x, f[1].x, f[2].x, f[3].x);
        float4 lo1 = make_float4(f[4].x, f[5].x, f[6].x, f[7].x);
        float4 hi0 = make_float4(f[0].y, f[1].y, f[2].y, f[3].y);
        float4 hi1 = make_float4(f[4].y, f[5].y, f[6].y, f[7].y);
        *(float4*)&outp[(size_t)(r0 + 2 * rp) * FF + c0]         = lo0;
        *(float4*)&outp[(size_t)(r0 + 2 * rp) * FF + c0 + 4]     = lo1;
        *(float4*)&outp[(size_t)(r0 + 2 * rp + 1) * FF + c0]     = hi0;
        *(float4*)&outp[(size_t)(r0 + 2 * rp + 1) * FF + c0 + 4] = hi1;
    }
}

// ---------------- K3: SpMM two-phase; grid (2048, 2) ----------------
__global__ __launch_bounds__(256) void k_spmm(const float* __restrict__ Ld,
                                              const float* __restrict__ Lu) {
    __shared__ float4 qv[8][64];
    __shared__ u16    qs[8][64];
    __shared__ float  yp[8][FF];
    int b = blockIdx.y;
    int t = threadIdx.x;
    int w = t >> 5, lane = t & 31;
    int row = (blockIdx.x << 1) + (w >> 2);
    int r = w & 3;
    const float* __restrict__ L = b ? Lu : Ld;
    const float4* __restrict__ Lr4 = (const float4*)(L + (size_t)row * NN + r * 1024);

    float4 v[8];
    #pragma unroll
    for (int it = 0; it < 8; it++) v[it] = __ldcs(&Lr4[it * 32 + lane]);

    unsigned msk[8]; int tot = 0;
    #pragma unroll
    for (int it = 0; it < 8; it++) {
        float4 q = v[it];
        bool any = (q.x != 0.f) || (q.y != 0.f) || (q.z != 0.f) || (q.w != 0.f);
        msk[it] = __ballot_sync(0xffffffffu, any);
        tot += __popc(msk[it]);
    }

    const float* __restrict__ xw1 = g_xw[b][1];
    int regidx = row * 4 + r;
    u16* __restrict__ nz = &g_nzj[b][(size_t)regidx * CAPR];
    int cbase = r * 1024;
    float acc0 = 0.f, acc1 = 0.f;
    int nzc = 0;

    if (tot <= 64) {
        int cnt = 0;
        #pragma unroll
        for (int it = 0; it < 8; it++) {
            unsigned m = msk[it];
            if ((m >> lane) & 1u) {
                int pos = cnt + __popc(m & ((1u << lane) - 1u));
                qv[w][pos] = v[it];
                qs[w][pos] = (u16)(it * 32 + lane);
            }
            cnt += __popc(m);
        }
        __syncwarp();
        for (int p = 0; p < cnt; p++) {
            float4 q = qv[w][p];
            int col0 = cbase + ((int)qs[w][p]) * 4;
            if (q.x != 0.f) { acc0 += q.x * xw1[(size_t)(col0 + 0) * FF + lane];
                              if (lane == 0 && nzc < CAPR) nz[nzc] = (u16)(col0 + 0); nzc++; }
            if (q.y != 0.f) { acc1 += q.y * xw1[(size_t)(col0 + 1) * FF + lane];
                              if (lane == 0 && nzc < CAPR) nz[nzc] = (u16)(col0 + 1); nzc++; }
            if (q.z != 0.f) { acc0 += q.z * xw1[(size_t)(col0 + 2) * FF + lane];
                              if (lane == 0 && nzc < CAPR) nz[nzc] = (u16)(col0 + 2); nzc++; }
            if (q.w != 0.f) { acc1 += q.w * xw1[(size_t)(col0 + 3) * FF + lane];
                              if (lane == 0 && nzc < CAPR) nz[nzc] = (u16)(col0 + 3); nzc++; }
        }
    } else {
        #pragma unroll
        for (int it = 0; it < 8; it++) {
            float4 q = v[it];
            unsigned mask = msk[it];
            while (mask) {
                int s = __ffs(mask) - 1; mask &= mask - 1;
                float u0 = __shfl_sync(0xffffffffu, q.x, s);
                float u1 = __shfl_sync(0xffffffffu, q.y, s);
                float u2 = __shfl_sync(0xffffffffu, q.z, s);
                float u3 = __shfl_sync(0xffffffffu, q.w, s);
                int col0 = cbase + it * 128 + s * 4;
                float uv[4] = {u0, u1, u2, u3};
                #pragma unroll
                for (int e = 0; e < 4; e++) {
                    if (uv[e] != 0.f) {
                        acc0 += uv[e] * xw1[(size_t)(col0 + e) * FF + lane];
                        if (lane == 0 && nzc < CAPR) nz[nzc] = (u16)(col0 + e);
                        nzc++;
                    }
                }
            }
        }
    }
    if (lane == 0) g_cnt[b][regidx] = (nzc < CAPR) ? nzc : CAPR;

    yp[w][lane] = acc0 + acc1;
    __syncthreads();
    if ((w & 3) == 0) {
        float s = g_xw[b][0][(size_t)row * FF + lane];
        #pragma unroll
        for (int ww = 0; ww < 4; ww++) s += yp[(w & 4) + ww][lane];
        g_y[b][(size_t)row * FF + lane] = s;
    }
}

// ---------------- K4: attention, warp per (row, branch); blocks of 4 rows x 2 branches ----------------
__global__ __launch_bounds__(256) void k_attn(float* __restrict__ out) {
    int t = threadIdx.x;
    int w = t >> 5, lane = t & 31;
    int r = w & 3;          // row within block
    int b = w >> 2;         // branch
    int i = blockIdx.x * 4 + r;
    const float NEGINF = __int_as_float(0xff800000u);
    __shared__ float sz1[4][FF];

    float s1i = g_s1[b][i];
    const float* __restrict__ s2 = g_s2[b];
    const float* __restrict__ y = g_y[b];
    int4 c4v = *(const int4*)&g_cnt[b][i * 4];
    int cnts[4] = {c4v.x, c4v.y, c4v.z, c4v.w};
    int tot = c4v.x + c4v.y + c4v.z + c4v.w;

    float bval;
    if (tot == 0) {   // fully-masked row: uniform softmax (improbable; correctness path)
        float tsum = 0.f;
        for (int j = 0; j < NN; j++) tsum += y[(size_t)j * FF + lane];
        bval = tsum * (1.f / NN);
    } else {
        // pass A: max of s2 over nz (leakyrelu monotone)
        float mx = NEGINF;
        #pragma unroll
        for (int rr = 0; rr < 4; rr++) {
            const u16* __restrict__ nzp = &g_nzj[b][(size_t)(i * 4 + rr) * CAPR];
            for (int p = lane; p < cnts[rr]; p += 32) mx = fmaxf(mx, s2[nzp[p]]);
        }
        #pragma unroll
        for (int d = 16; d; d >>= 1) mx = fmaxf(mx, __shfl_xor_sync(0xffffffffu, mx, d));
        float M = lrelu(s1i + mx);

        float l0 = 0.f, l1 = 0.f, l2 = 0.f, l3 = 0.f;
        float z0 = 0.f, z1 = 0.f, z2 = 0.f, z3 = 0.f;
        #pragma unroll
        for (int rr = 0; rr < 4; rr++) {
            const u16* __restrict__ nzp = &g_nzj[b][(size_t)(i * 4 + rr) * CAPR];
            int c = cnts[rr];
            int p = 0;
            for (; p + 3 < c; p += 4) {
                int j0 = nzp[p], j1 = nzp[p + 1], j2 = nzp[p + 2], j3 = nzp[p + 3];
                float pw0 = __expf(lrelu(s1i + s2[j0]) - M);
                float pw1 = __expf(lrelu(s1i + s2[j1]) - M);
                float pw2 = __expf(lrelu(s1i + s2[j2]) - M);
                float pw3 = __expf(lrelu(s1i + s2[j3]) - M);
                float y0 = y[(size_t)j0 * FF + lane];
                float y1 = y[(size_t)j1 * FF + lane];
                float y2 = y[(size_t)j2 * FF + lane];
                float y3 = y[(size_t)j3 * FF + lane];
                l0 += pw0; l1 += pw1; l2 += pw2; l3 += pw3;
                z0 += pw0 * y0; z1 += pw1 * y1; z2 += pw2 * y2; z3 += pw3 * y3;
            }
            for (; p < c; p++) {
                int j0 = nzp[p];
                float pw0 = __expf(lrelu(s1i + s2[j0]) - M);
                l0 += pw0;
                z0 += pw0 * y[(size_t)j0 * FF + lane];
            }
        }
        bval = ((z0 + z1) + (z2 + z3)) / ((l0 + l1) + (l2 + l3));
    }

    if (b == 1) sz1[r][lane] = bval;
    __syncthreads();
    if (b == 0) {
        float val = bval + sz1[r][lane];
        #pragma unroll
        for (int s = 0; s < KSPLIT; s++) val += __ldcs(&g_part[s][(size_t)i * FF + lane]);
        out[(size_t)i * FF + lane] = val;
    }
}

extern "C" void kernel_launch(void* const* d_in, const int* in_sizes, int n_in,
                              void* d_out, int out_size) {
    const float* x    = (const float*)d_in[0];
    const float* Ld   = (const float*)d_in[1];
    const float* Lu   = (const float*)d_in[2];
    const float* P    = (const float*)d_in[3];
    const float* W1   = (const float*)d_in[4];
    const float* W2   = (const float*)d_in[5];
    const float* W0   = (const float*)d_in[6];
    const float* att1 = (const float*)d_in[7];
    const float* att2 = (const float*)d_in[8];
    float* out = (float*)d_out;

    cudaFuncSetAttribute(k_pgemm, cudaFuncAttributeMaxDynamicSharedMemorySize, PGSMEM);
    k_pre<<<NN / 4, 128>>>(x, W1, W2, W0, att1, att2);
    k_pgemm<<<dim3(NN / 512, KSPLIT), 256, PGSMEM>>>(P);
    k_spmm<<<dim3(2048, 2), 256>>>(Ld, Lu);
    k_attn<<<NN / 4, 256>>>(out);
}

// round 7
// speedup vs baseline: 1.6934x; 1.0896x over previous
#include <cuda_runtime.h>
#include <cstdint>

typedef unsigned long long ull;
typedef unsigned short u16;

#define NN 4096
#define FF 32
#define NEG_SLOPE 0.2f
#define CAPREG 64
#define CAPROW 256
#define KSPLIT 16
#define RP 520
#define PGSMEM (32 * RP * 4 + 32 * 40 * 8)

__device__ float g_xw[2][2][NN * FF];
__device__ float g_xw0[NN * FF];
__device__ float g_s1[2][NN];
__device__ float g_s2[2][NN];
__device__ float g_y[2][NN * FF];
__device__ u16   g_nzj[2][(size_t)NN * CAPROW];
__device__ int   g_cnt[2][NN];
__device__ float g_part[KSPLIT][NN * FF];

__device__ __forceinline__ ull ffma2(ull a, ull b, ull c) {
    ull d;
    asm("fma.rn.f32x2 %0, %1, %2, %3;" : "=l"(d) : "l"(a), "l"(b), "l"(c));
    return d;
}
__device__ __forceinline__ ull pack2(float lo, float hi) {
    ull d;
    asm("mov.b64 %0, {%1, %2};" : "=l"(d) : "f"(lo), "f"(hi));
    return d;
}
__device__ __forceinline__ float2 unpack2(ull v) {
    float2 r;
    asm("mov.b64 {%0, %1}, %2;" : "=f"(r.x), "=f"(r.y) : "l"(v));
    return r;
}
__device__ __forceinline__ float warp_sum(float p) {
    #pragma unroll
    for (int d = 16; d; d >>= 1) p += __shfl_xor_sync(0xffffffffu, p, d);
    return p;
}
__device__ __forceinline__ float lrelu(float e) {
    return fmaxf(e, NEG_SLOPE * e);
}

// ---------------- K1: xw[k] = x@W[k], xw0 = x@W0, s1/s2 vectors ----------------
__global__ void k_pre(const float* __restrict__ x, const float* __restrict__ W1,
                      const float* __restrict__ W2, const float* __restrict__ W0,
                      const float* __restrict__ att1, const float* __restrict__ att2) {
    int w = threadIdx.x >> 5, lane = threadIdx.x & 31;
    int i = blockIdx.x * 4 + w;
    float xv = x[i * FF + lane];

    float o0 = 0.f, o1 = 0.f, o2 = 0.f, o3 = 0.f, o4 = 0.f;
    #pragma unroll
    for (int f = 0; f < FF; f++) {
        float xf = __shfl_sync(0xffffffffu, xv, f);
        o0 += xf * __ldg(&W1[f * FF + lane]);
        o1 += xf * __ldg(&W1[1024 + f * FF + lane]);
        o2 += xf * __ldg(&W2[f * FF + lane]);
        o3 += xf * __ldg(&W2[1024 + f * FF + lane]);
        o4 += xf * __ldg(&W0[f * FF + lane]);
    }
    g_xw[0][0][i * FF + lane] = o0;
    g_xw[0][1][i * FF + lane] = o1;
    g_xw[1][0][i * FF + lane] = o2;
    g_xw[1][1][i * FF + lane] = o3;
    g_xw0[i * FF + lane] = o4;

    float p;
    p = warp_sum(o0 * __ldg(&att1[lane]) + o1 * __ldg(&att1[FF + lane]));
    if (lane == 0) g_s1[0][i] = p;
    p = warp_sum(o0 * __ldg(&att1[2 * FF + lane]) + o1 * __ldg(&att1[3 * FF + lane]));
    if (lane == 0) g_s2[0][i] = p;
    p = warp_sum(o2 * __ldg(&att2[lane]) + o3 * __ldg(&att2[FF + lane]));
    if (lane == 0) g_s1[1][i] = p;
    p = warp_sum(o2 * __ldg(&att2[2 * FF + lane]) + o3 * __ldg(&att2[3 * FF + lane]));
    if (lane == 0) g_s2[1][i] = p;
}

// ---------------- K2: P-GEMM  BM=512, 8x8 thread tile, f32x2, KSPLIT=16 ----------------
__global__ __launch_bounds__(256, 1) void k_pgemm(const float* __restrict__ P) {
    extern __shared__ __align__(16) unsigned char smraw[];
    float* Ps = (float*)smraw;
    ull*   Bs = (ull*)(smraw + 32 * RP * 4);

    int t = threadIdx.x;
    int rb = blockIdx.x * 512, k0 = blockIdx.y * 256;
    int c4 = t & 7, row0 = t >> 3;
    int sw2c4 = ((c4 & 3) << 3) ^ ((c4 >> 2) << 2);
    int kq = t >> 3, c4b = t & 7;
    int bbase = kq * 40 + (c4b >> 1) * 10 + (c4b & 1) * 4;
    int rowg = t >> 2, colg = t & 3;
    int rXor = ((rowg >> 2) & 7) << 2;

    const float4* __restrict__ P4 = (const float4*)P;
    const float4* __restrict__ B4 = (const float4*)g_xw0;

    ull acc[4][8];
    #pragma unroll
    for (int i = 0; i < 4; i++)
        #pragma unroll
        for (int j = 0; j < 8; j++) acc[i][j] = 0ull;

    float4 pv[16]; float4 bv;
    #pragma unroll
    for (int j = 0; j < 16; j++)
        pv[j] = P4[(size_t)(rb + row0 + 32 * j) * (NN / 4) + (k0 >> 2) + c4];
    bv = B4[(size_t)(k0 + kq) * (FF / 4) + c4b];

    for (int kt = 0; kt < 8; kt++) {
        __syncthreads();
        #pragma unroll
        for (int j = 0; j < 16; j++) {
            int X = sw2c4 ^ ((j & 7) << 2);
            int rbase = 32 * j + (row0 ^ X);
            Ps[(4 * c4 + 0) * RP + rbase] = pv[j].x;
            Ps[(4 * c4 + 1) * RP + rbase] = pv[j].y;
            Ps[(4 * c4 + 2) * RP + rbase] = pv[j].z;
            Ps[(4 * c4 + 3) * RP + rbase] = pv[j].w;
        }
        Bs[bbase + 0] = pack2(bv.x, bv.x);
        Bs[bbase + 1] = pack2(bv.y, bv.y);
        Bs[bbase + 2] = pack2(bv.z, bv.z);
        Bs[bbase + 3] = pack2(bv.w, bv.w);
        __syncthreads();
        if (kt < 7) {
            int kk = k0 + (kt + 1) * 32;
            #pragma unroll
            for (int j = 0; j < 16; j++)
                pv[j] = P4[(size_t)(rb + row0 + 32 * j) * (NN / 4) + (kk >> 2) + c4];
            bv = B4[(size_t)(kk + kq) * (FF / 4) + c4b];
        }
        #pragma unroll
        for (int k = 0; k < 32; k++) {
            int c4k = k >> 2;
            int XA = (((c4k & 3) << 3) ^ ((c4k >> 2) << 2)) ^ rXor;
            const ulonglong2 pA = *(const ulonglong2*)&Ps[k * RP + ((rowg * 8) ^ XA)];
            const ulonglong2 pB = *(const ulonglong2*)&Ps[k * RP + ((rowg * 8 + 4) ^ XA)];
            const ull* bp = &Bs[k * 40 + colg * 10];
            const ulonglong2 b01 = *(const ulonglong2*)(bp + 0);
            const ulonglong2 b23 = *(const ulonglong2*)(bp + 2);
            const ulonglong2 b45 = *(const ulonglong2*)(bp + 4);
            const ulonglong2 b67 = *(const ulonglong2*)(bp + 6);
            ull pp[4] = {pA.x, pA.y, pB.x, pB.y};
            ull bbv[8] = {b01.x, b01.y, b23.x, b23.y, b45.x, b45.y, b67.x, b67.y};
            #pragma unroll
            for (int i = 0; i < 4; i++)
                #pragma unroll
                for (int j = 0; j < 8; j++)
                    acc[i][j] = ffma2(pp[i], bbv[j], acc[i][j]);
        }
    }
    float* __restrict__ outp = g_part[blockIdx.y];
    int r0 = rb + rowg * 8, c0 = colg * 8;
    #pragma unroll
    for (int rp = 0; rp < 4; rp++) {
        float2 f[8];
        #pragma unroll
        for (int c = 0; c < 8; c++) f[c] = unpack2(acc[rp][c]);
        float4 lo0 = make_float4(f[0].x, f[1].x, f[2].x, f[3].x);
        float4 lo1 = make_float4(f[4].x, f[5].x, f[6].x, f[7].x);
        float4 hi0 = make_float4(f[0].y, f[1].y, f[2].y, f[3].y);
        float4 hi1 = make_float4(f[4].y, f[5].y, f[6].y, f[7].y);
        *(float4*)&outp[(size_t)(r0 + 2 * rp) * FF + c0]         = lo0;
        *(float4*)&outp[(size_t)(r0 + 2 * rp) * FF + c0 + 4]     = lo1;
        *(float4*)&outp[(size_t)(r0 + 2 * rp + 1) * FF + c0]     = hi0;
        *(float4*)&outp[(size_t)(r0 + 2 * rp + 1) * FF + c0 + 4] = hi1;
    }
}

// ---------------- K3: SpMM two-phase + merged per-row nz lists; grid (2048, 2) ----------------
__global__ __launch_bounds__(256) void k_spmm(const float* __restrict__ Ld,
                                              const float* __restrict__ Lu) {
    __shared__ float4 qv[8][64];
    __shared__ u16    qs[8][64];
    __shared__ u16    rl[2][4][CAPREG];   // per-row, per-region col list
    __shared__ int    rc[2][4];
    __shared__ float  yp[8][FF];
    int b = blockIdx.y;
    int t = threadIdx.x;
    int w = t >> 5, lane = t & 31;
    int rowb = w >> 2;
    int row = (blockIdx.x << 1) + rowb;
    int r = w & 3;
    const float* __restrict__ L = b ? Lu : Ld;
    const float4* __restrict__ Lr4 = (const float4*)(L + (size_t)row * NN + r * 1024);

    float4 v[8];
    #pragma unroll
    for (int it = 0; it < 8; it++) v[it] = __ldcs(&Lr4[it * 32 + lane]);

    unsigned msk[8]; int tot = 0;
    #pragma unroll
    for (int it = 0; it < 8; it++) {
        float4 q = v[it];
        bool any = (q.x != 0.f) || (q.y != 0.f) || (q.z != 0.f) || (q.w != 0.f);
        msk[it] = __ballot_sync(0xffffffffu, any);
        tot += __popc(msk[it]);
    }

    const float* __restrict__ xw1 = g_xw[b][1];
    int cbase = r * 1024;
    float acc0 = 0.f, acc1 = 0.f;
    int nzc = 0;

    if (tot <= 64) {
        int cnt = 0;
        #pragma unroll
        for (int it = 0; it < 8; it++) {
            unsigned m = msk[it];
            if ((m >> lane) & 1u) {
                int pos = cnt + __popc(m & ((1u << lane) - 1u));
                qv[w][pos] = v[it];
                qs[w][pos] = (u16)(it * 32 + lane);
            }
            cnt += __popc(m);
        }
        __syncwarp();
        for (int p = 0; p < cnt; p++) {
            float4 q = qv[w][p];
            int col0 = cbase + ((int)qs[w][p]) * 4;
            if (q.x != 0.f) { acc0 += q.x * xw1[(size_t)(col0 + 0) * FF + lane];
                              if (lane == 0 && nzc < CAPREG) rl[rowb][r][nzc] = (u16)(col0 + 0); nzc++; }
            if (q.y != 0.f) { acc1 += q.y * xw1[(size_t)(col0 + 1) * FF + lane];
                              if (lane == 0 && nzc < CAPREG) rl[rowb][r][nzc] = (u16)(col0 + 1); nzc++; }
            if (q.z != 0.f) { acc0 += q.z * xw1[(size_t)(col0 + 2) * FF + lane];
                              if (lane == 0 && nzc < CAPREG) rl[rowb][r][nzc] = (u16)(col0 + 2); nzc++; }
            if (q.w != 0.f) { acc1 += q.w * xw1[(size_t)(col0 + 3) * FF + lane];
                              if (lane == 0 && nzc < CAPREG) rl[rowb][r][nzc] = (u16)(col0 + 3); nzc++; }
        }
    } else {
        #pragma unroll
        for (int it = 0; it < 8; it++) {
            float4 q = v[it];
            unsigned mask = msk[it];
            while (mask) {
                int s = __ffs(mask) - 1; mask &= mask - 1;
                float u0 = __shfl_sync(0xffffffffu, q.x, s);
                float u1 = __shfl_sync(0xffffffffu, q.y, s);
                float u2 = __shfl_sync(0xffffffffu, q.z, s);
                float u3 = __shfl_sync(0xffffffffu, q.w, s);
                int col0 = cbase + it * 128 + s * 4;
                float uv[4] = {u0, u1, u2, u3};
                #pragma unroll
                for (int e = 0; e < 4; e++) {
                    if (uv[e] != 0.f) {
                        acc0 += uv[e] * xw1[(size_t)(col0 + e) * FF + lane];
                        if (lane == 0 && nzc < CAPREG) rl[rowb][r][nzc] = (u16)(col0 + e);
                        nzc++;
                    }
                }
            }
        }
    }
    if (nzc > CAPREG) nzc = CAPREG;
    if (lane == 0) rc[rowb][r] = nzc;

    yp[w][lane] = acc0 + acc1;
    __syncthreads();

    // merged copy: region r writes its list at prefix offset
    {
        int c0 = rc[rowb][0], c1 = rc[rowb][1], c2 = rc[rowb][2], c3 = rc[rowb][3];
        int off = (r > 0 ? c0 : 0) + (r > 1 ? c1 : 0) + (r > 2 ? c2 : 0);
        int myc = rc[rowb][r];
        u16* __restrict__ dst = &g_nzj[b][(size_t)row * CAPROW + off];
        for (int p = lane; p < myc; p += 32) dst[p] = rl[rowb][r][p];
        if (r == 0 && lane == 0) g_cnt[b][row] = c0 + c1 + c2 + c3;
    }

    if ((w & 3) == 0) {
        float s = g_xw[b][0][(size_t)row * FF + lane];
        #pragma unroll
        for (int ww = 0; ww < 4; ww++) s += yp[(w & 4) + ww][lane];
        g_y[b][(size_t)row * FF + lane] = s;
    }
}

// ---------------- K4: attention v3 — staged softmax weights, pure gather pass ----------------
__global__ __launch_bounds__(256) void k_attn(float* __restrict__ out) {
    __shared__ float pwbuf[8][CAPROW];
    __shared__ float sz1[4][FF];
    int t = threadIdx.x;
    int w = t >> 5, lane = t & 31;
    int r = w & 3;
    int b = w >> 2;
    int i = blockIdx.x * 4 + r;
    const float NEGINF = __int_as_float(0xff800000u);

    float s1i = g_s1[b][i];
    const float* __restrict__ s2 = g_s2[b];
    const float* __restrict__ y = g_y[b];
    int cnt = g_cnt[b][i];
    const u16* __restrict__ nzp = &g_nzj[b][(size_t)i * CAPROW];

    float bval;
    if (cnt == 0) {   // fully-masked row: uniform softmax (improbable; correctness path)
        float tsum = 0.f;
        for (int j = 0; j < NN; j++) tsum += y[(size_t)j * FF + lane];
        bval = tsum * (1.f / NN);
    } else {
        // pass A: row max of s2 over nz
        float mx = NEGINF;
        for (int p = lane; p < cnt; p += 32) mx = fmaxf(mx, s2[nzp[p]]);
        #pragma unroll
        for (int d = 16; d; d >>= 1) mx = fmaxf(mx, __shfl_xor_sync(0xffffffffu, mx, d));
        float M = lrelu(s1i + mx);

        // pass B: weights, lanes parallel over nz; stage in smem
        float l = 0.f;
        for (int p = lane; p < cnt; p += 32) {
            float pw = __expf(lrelu(s1i + s2[nzp[p]]) - M);
            pwbuf[w][p] = pw;
            l += pw;
        }
        l = warp_sum(l);
        __syncwarp();

        // pass C: pure gather, unroll 8, 4 accumulators
        float z0 = 0.f, z1 = 0.f, z2 = 0.f, z3 = 0.f;
        int p = 0;
        for (; p + 8 <= cnt; p += 8) {
            int j0 = nzp[p + 0], j1 = nzp[p + 1], j2 = nzp[p + 2], j3 = nzp[p + 3];
            int j4 = nzp[p + 4], j5 = nzp[p + 5], j6 = nzp[p + 6], j7 = nzp[p + 7];
            float y0 = y[(size_t)j0 * FF + lane];
            float y1 = y[(size_t)j1 * FF + lane];
            float y2 = y[(size_t)j2 * FF + lane];
            float y3 = y[(size_t)j3 * FF + lane];
            float y4 = y[(size_t)j4 * FF + lane];
            float y5 = y[(size_t)j5 * FF + lane];
            float y6 = y[(size_t)j6 * FF + lane];
            float y7 = y[(size_t)j7 * FF + lane];
            z0 += pwbuf[w][p + 0] * y0;
            z1 += pwbuf[w][p + 1] * y1;
            z2 += pwbuf[w][p + 2] * y2;
            z3 += pwbuf[w][p + 3] * y3;
            z0 += pwbuf[w][p + 4] * y4;
            z1 += pwbuf[w][p + 5] * y5;
            z2 += pwbuf[w][p + 6] * y6;
            z3 += pwbuf[w][p + 7] * y7;
        }
        for (; p < cnt; p++)
            z0 += pwbuf[w][p] * y[(size_t)nzp[p] * FF + lane];
        bval = ((z0 + z1) + (z2 + z3)) / l;
    }

    if (b == 1) sz1[r][lane] = bval;
    __syncthreads();
    if (b == 0) {
        float val = bval + sz1[r][lane];
        #pragma unroll
        for (int s = 0; s < KSPLIT; s++) val += __ldcs(&g_part[s][(size_t)i * FF + lane]);
        out[(size_t)i * FF + lane] = val;
    }
}

extern "C" void kernel_launch(void* const* d_in, const int* in_sizes, int n_in,
                              void* d_out, int out_size) {
    const float* x    = (const float*)d_in[0];
    const float* Ld   = (const float*)d_in[1];
    const float* Lu   = (const float*)d_in[2];
    const float* P    = (const float*)d_in[3];
    const float* W1   = (const float*)d_in[4];
    const float* W2   = (const float*)d_in[5];
    const float* W0   = (const float*)d_in[6];
    const float* att1 = (const float*)d_in[7];
    const float* att2 = (const float*)d_in[8];
    float* out = (float*)d_out;

    cudaFuncSetAttribute(k_pgemm, cudaFuncAttributeMaxDynamicSharedMemorySize, PGSMEM);
    k_pre<<<NN / 4, 128>>>(x, W1, W2, W0, att1, att2);
    k_pgemm<<<dim3(NN / 512, KSPLIT), 256, PGSMEM>>>(P);
    k_spmm<<<dim3(2048, 2), 256>>>(Ld, Lu);
    k_attn<<<NN / 4, 256>>>(out);
}